// round 1
// baseline (speedup 1.0000x reference)
#include <cuda_runtime.h>
#include <cuda_bf16.h>
#include <math.h>

#define B_ 4
#define S_ 2048
#define D_ 1024
#define H_ 16
#define HD_ 64
#define F_ 4096
#define E_ 8
#define TOPK_ 2
#define T_ (B_*S_)                    // 8192 tokens
#define NSLOT_ (T_*TOPK_ + E_*128)    // 17408 padded expert slots

// ------------------------- static device scratch -------------------------
__device__ float g_q[(size_t)T_*D_];
__device__ float g_k[(size_t)T_*D_];
__device__ float g_v[(size_t)T_*D_];
__device__ float g_attn[(size_t)T_*D_];
__device__ float g_proj[(size_t)T_*D_];
__device__ float g_x1[(size_t)T_*D_];
__device__ float g_macc[(size_t)T_*D_];
__device__ float g_h[(size_t)NSLOT_*F_];
__device__ int   g_slot_tok[NSLOT_];
__device__ float g_slot_w[NSLOT_];
__device__ int   g_texp[T_*TOPK_];
__device__ int   g_tpos[T_*TOPK_];
__device__ float g_tw[T_*TOPK_];
__device__ int   g_cnt[E_];
__device__ float g_rsum[E_];
__device__ int   g_offs[E_+1];

__device__ __forceinline__ float gelu_f(float z) {
    return 0.5f * z * (1.0f + erff(z * 0.70710678118654752f));
}

// ------------------------- generic SGEMM: C = A@W + bias -------------------------
// A [M,Kd] row-major, W [Kd,N] row-major, bias [N]. M,N multiples of 128, Kd of 8.
__global__ void __launch_bounds__(256) k_gemm_bias(
    const float* __restrict__ A, const float* __restrict__ W,
    const float* __restrict__ bias, float* __restrict__ C,
    int M, int N, int Kd)
{
    __shared__ float As[8][128];
    __shared__ float Bs[8][128];
    const int tid   = threadIdx.x;
    const int tileN = blockIdx.x * 128;
    const int tileM = blockIdx.y * 128;
    const int tr = tid >> 4, tc = tid & 15;
    const int arow = tid >> 1, ac4 = (tid & 1) * 4;
    const int brow = tid >> 5, bc4 = (tid & 31) * 4;

    float acc[8][8];
    #pragma unroll
    for (int i = 0; i < 8; i++) {
        #pragma unroll
        for (int j = 0; j < 8; j++) acc[i][j] = 0.f;
    }

    const float* Aptr = A + (size_t)(tileM + arow) * Kd + ac4;
    const float* Wptr = W + (size_t)brow * N + tileN + bc4;

    for (int k0 = 0; k0 < Kd; k0 += 8) {
        float4 av = *(const float4*)(Aptr + k0);
        As[ac4+0][arow] = av.x; As[ac4+1][arow] = av.y;
        As[ac4+2][arow] = av.z; As[ac4+3][arow] = av.w;
        *(float4*)&Bs[brow][bc4] = *(const float4*)(Wptr + (size_t)k0 * N);
        __syncthreads();
        #pragma unroll
        for (int kk = 0; kk < 8; kk++) {
            float ra[8], rb[8];
            #pragma unroll
            for (int i = 0; i < 8; i++) ra[i] = As[kk][tr*8+i];
            #pragma unroll
            for (int j = 0; j < 8; j++) rb[j] = Bs[kk][tc*8+j];
            #pragma unroll
            for (int i = 0; i < 8; i++) {
                #pragma unroll
                for (int j = 0; j < 8; j++) acc[i][j] += ra[i] * rb[j];
            }
        }
        __syncthreads();
    }
    #pragma unroll
    for (int i = 0; i < 8; i++) {
        float* crow = C + (size_t)(tileM + tr*8 + i) * N + tileN;
        #pragma unroll
        for (int j = 0; j < 8; j++)
            crow[tc*8+j] = acc[i][j] + bias[tileN + tc*8 + j];
    }
}

// ------------------------- flash attention -------------------------
// grid (S/64, H, B), 256 threads; q/k/v/attn are [T, D] with head slice h*64.
__global__ void __launch_bounds__(256) k_flash(
    const float* __restrict__ q, const float* __restrict__ k,
    const float* __restrict__ v, float* __restrict__ o)
{
    extern __shared__ float sm[];
    float* Qs  = sm;                 // 64 x 65
    float* Ks  = Qs + 64*65;
    float* Vs  = Ks + 64*65;
    float* Ss  = Vs + 64*65;
    float* mrow = Ss + 64*65;        // 64
    float* lrow = mrow + 64;
    float* arow = lrow + 64;

    const int tid = threadIdx.x;
    const int q0  = blockIdx.x * 64;
    const int h   = blockIdx.y;
    const int b   = blockIdx.z;
    const size_t base = (size_t)b * S_ * D_ + (size_t)h * HD_;

    for (int idx = tid; idx < 64*64; idx += 256) {
        int r = idx >> 6, c = idx & 63;
        Qs[r*65 + c] = q[base + (size_t)(q0 + r) * D_ + c];
    }
    if (tid < 64) { mrow[tid] = -1e30f; lrow[tid] = 0.f; }

    const int tr = tid >> 4, tc = tid & 15;
    float Oacc[4][4];
    #pragma unroll
    for (int i = 0; i < 4; i++) {
        #pragma unroll
        for (int j = 0; j < 4; j++) Oacc[i][j] = 0.f;
    }
    __syncthreads();

    for (int kt = 0; kt < S_; kt += 64) {
        for (int idx = tid; idx < 64*64; idx += 256) {
            int r = idx >> 6, c = idx & 63;
            Ks[r*65 + c] = k[base + (size_t)(kt + r) * D_ + c];
            Vs[r*65 + c] = v[base + (size_t)(kt + r) * D_ + c];
        }
        __syncthreads();

        float s[4][4];
        #pragma unroll
        for (int i = 0; i < 4; i++) {
            #pragma unroll
            for (int j = 0; j < 4; j++) s[i][j] = 0.f;
        }
        #pragma unroll 4
        for (int d = 0; d < 64; d++) {
            float ra[4], rb[4];
            #pragma unroll
            for (int i = 0; i < 4; i++) ra[i] = Qs[(tr*4+i)*65 + d];
            #pragma unroll
            for (int j = 0; j < 4; j++) rb[j] = Ks[(tc*4+j)*65 + d];
            #pragma unroll
            for (int i = 0; i < 4; i++) {
                #pragma unroll
                for (int j = 0; j < 4; j++) s[i][j] += ra[i] * rb[j];
            }
        }
        #pragma unroll
        for (int i = 0; i < 4; i++) {
            #pragma unroll
            for (int j = 0; j < 4; j++)
                Ss[(tr*4+i)*65 + tc*4+j] = s[i][j] * 0.125f;
        }
        __syncthreads();

        if (tid < 64) {
            float m_old = mrow[tid];
            float mx = m_old;
            float* srow = Ss + tid * 65;
            for (int c = 0; c < 64; c++) mx = fmaxf(mx, srow[c]);
            float al = __expf(m_old - mx);
            float lsum = 0.f;
            for (int c = 0; c < 64; c++) {
                float p = __expf(srow[c] - mx);
                srow[c] = p;
                lsum += p;
            }
            mrow[tid] = mx;
            lrow[tid] = lrow[tid] * al + lsum;
            arow[tid] = al;
        }
        __syncthreads();

        float al[4];
        #pragma unroll
        for (int i = 0; i < 4; i++) al[i] = arow[tr*4+i];
        #pragma unroll
        for (int i = 0; i < 4; i++) {
            #pragma unroll
            for (int j = 0; j < 4; j++) Oacc[i][j] *= al[i];
        }
        #pragma unroll 4
        for (int d = 0; d < 64; d++) {
            float ra[4], rb[4];
            #pragma unroll
            for (int i = 0; i < 4; i++) ra[i] = Ss[(tr*4+i)*65 + d];
            #pragma unroll
            for (int j = 0; j < 4; j++) rb[j] = Vs[d*65 + tc*4+j];
            #pragma unroll
            for (int i = 0; i < 4; i++) {
                #pragma unroll
                for (int j = 0; j < 4; j++) Oacc[i][j] += ra[i] * rb[j];
            }
        }
        __syncthreads();
    }

    #pragma unroll
    for (int i = 0; i < 4; i++) {
        float invl = 1.f / lrow[tr*4+i];
        #pragma unroll
        for (int j = 0; j < 4; j++)
            o[base + (size_t)(q0 + tr*4 + i) * D_ + tc*4 + j] = Oacc[i][j] * invl;
    }
}

// ------------------------- residual + layernorm -------------------------
__global__ void __launch_bounds__(256) k_add_ln(
    const float* __restrict__ x, const float* __restrict__ r,
    const float* __restrict__ g, const float* __restrict__ be,
    float* __restrict__ out, int has_r)
{
    __shared__ float red[8];
    __shared__ float s_mu, s_inv;
    const int t = blockIdx.x;
    const int tid = threadIdx.x;
    const float* xr = x + (size_t)t * D_;
    const float* rr = r + (size_t)t * D_;

    float v[4];
    float s = 0.f;
    #pragma unroll
    for (int i = 0; i < 4; i++) {
        int idx = tid + i * 256;
        v[i] = xr[idx] + (has_r ? rr[idx] : 0.f);
        s += v[i];
    }
    #pragma unroll
    for (int o = 16; o > 0; o >>= 1) s += __shfl_down_sync(0xffffffffu, s, o);
    if ((tid & 31) == 0) red[tid >> 5] = s;
    __syncthreads();
    if (tid < 8) {
        s = red[tid];
        #pragma unroll
        for (int o = 4; o > 0; o >>= 1) s += __shfl_down_sync(0xffu, s, o);
        if (tid == 0) s_mu = s * (1.f / D_);
    }
    __syncthreads();
    const float mu = s_mu;
    float sq = 0.f;
    #pragma unroll
    for (int i = 0; i < 4; i++) { float d = v[i] - mu; sq += d * d; }
    #pragma unroll
    for (int o = 16; o > 0; o >>= 1) sq += __shfl_down_sync(0xffffffffu, sq, o);
    __syncthreads();
    if ((tid & 31) == 0) red[tid >> 5] = sq;
    __syncthreads();
    if (tid < 8) {
        sq = red[tid];
        #pragma unroll
        for (int o = 4; o > 0; o >>= 1) sq += __shfl_down_sync(0xffu, sq, o);
        if (tid == 0) s_inv = rsqrtf(sq * (1.f / D_) + 1e-5f);
    }
    __syncthreads();
    const float inv = s_inv;
    #pragma unroll
    for (int i = 0; i < 4; i++) {
        int idx = tid + i * 256;
        out[(size_t)t * D_ + idx] = (v[i] - mu) * inv * g[idx] + be[idx];
    }
}

// ------------------------- MoE routing -------------------------
__global__ void k_init_small() {
    int i = threadIdx.x;
    if (i < E_) { g_cnt[i] = 0; g_rsum[i] = 0.f; }
}
__global__ void k_init_slots() {
    int i = blockIdx.x * 256 + threadIdx.x;
    if (i < NSLOT_) g_slot_tok[i] = -1;
}
__global__ void k_copy_macc() {
    size_t i = (size_t)blockIdx.x * 256 + threadIdx.x;
    g_macc[i] = g_x1[i];
}

// one warp per token: gate logits, softmax, top-2, slot assignment, aux accumulators
__global__ void __launch_bounds__(256) k_routing(
    const float* __restrict__ gateW, const float* __restrict__ gateb)
{
    const int gtid = blockIdx.x * blockDim.x + threadIdx.x;
    const int t = gtid >> 5;
    const int lane = gtid & 31;
    if (t >= T_) return;
    const float* xr = g_x1 + (size_t)t * D_;
    float acc[E_];
    #pragma unroll
    for (int e = 0; e < E_; e++) acc[e] = 0.f;
    for (int d = lane; d < D_; d += 32) {
        float xv = xr[d];
        const float* gw = gateW + (size_t)d * E_;
        #pragma unroll
        for (int e = 0; e < E_; e++) acc[e] += xv * gw[e];
    }
    #pragma unroll
    for (int e = 0; e < E_; e++) {
        #pragma unroll
        for (int o = 16; o > 0; o >>= 1)
            acc[e] += __shfl_down_sync(0xffffffffu, acc[e], o);
    }
    if (lane == 0) {
        float p[E_];
        float mx = -1e30f;
        #pragma unroll
        for (int e = 0; e < E_; e++) { acc[e] += gateb[e]; mx = fmaxf(mx, acc[e]); }
        float ssum = 0.f;
        #pragma unroll
        for (int e = 0; e < E_; e++) { p[e] = expf(acc[e] - mx); ssum += p[e]; }
        float invs = 1.f / ssum;
        #pragma unroll
        for (int e = 0; e < E_; e++) { p[e] *= invs; atomicAdd(&g_rsum[e], p[e]); }
        int i0 = 0;
        #pragma unroll
        for (int e = 1; e < E_; e++) if (p[e] > p[i0]) i0 = e;
        int i1 = -1;
        #pragma unroll
        for (int e = 0; e < E_; e++)
            if (e != i0 && (i1 < 0 || p[e] > p[i1])) i1 = e;
        float wsum = p[i0] + p[i1];
        int pos0 = atomicAdd(&g_cnt[i0], 1);
        int pos1 = atomicAdd(&g_cnt[i1], 1);
        g_texp[2*t]   = i0; g_tpos[2*t]   = pos0; g_tw[2*t]   = p[i0] / wsum;
        g_texp[2*t+1] = i1; g_tpos[2*t+1] = pos1; g_tw[2*t+1] = p[i1] / wsum;
    }
}

__global__ void k_scan() {
    if (threadIdx.x == 0 && blockIdx.x == 0) {
        int o = 0;
        for (int e = 0; e < E_; e++) {
            g_offs[e] = o;
            o += ((g_cnt[e] + 127) >> 7) << 7;   // pad each expert to 128 rows
        }
        g_offs[E_] = o;
    }
}

__global__ void k_fill_slots() {
    int i = blockIdx.x * 256 + threadIdx.x;
    if (i >= T_ * TOPK_) return;
    int e = g_texp[i];
    int slot = g_offs[e] + g_tpos[i];
    g_slot_tok[slot] = i >> 1;
    g_slot_w[slot] = g_tw[i];
}

// ------------------------- expert FFN layer 1: h = gelu(x1[tok] @ eW1[e] + eb1[e]) -------------------------
__global__ void __launch_bounds__(256) k_expert_ffn1(
    const float* __restrict__ eW1, const float* __restrict__ eb1)
{
    __shared__ float As[8][128];
    __shared__ float Bs[8][128];
    const int tid   = threadIdx.x;
    const int tileN = blockIdx.x * 128;
    const int tileM = blockIdx.y * 128;
    if (tileM >= g_offs[E_]) return;
    int e = 0;
    #pragma unroll
    for (int i = 1; i < E_; i++) if (tileM >= g_offs[i]) e = i;
    const float* W    = eW1 + (size_t)e * D_ * F_;
    const float* bias = eb1 + (size_t)e * F_;

    const int tr = tid >> 4, tc = tid & 15;
    const int arow = tid >> 1, ac4 = (tid & 1) * 4;
    const int brow = tid >> 5, bc4 = (tid & 31) * 4;

    const int atok = g_slot_tok[tileM + arow];
    const float* Aptr = (atok >= 0) ? (g_x1 + (size_t)atok * D_ + ac4) : nullptr;
    const float* Wptr = W + (size_t)brow * F_ + tileN + bc4;

    float acc[8][8];
    #pragma unroll
    for (int i = 0; i < 8; i++) {
        #pragma unroll
        for (int j = 0; j < 8; j++) acc[i][j] = 0.f;
    }
    for (int k0 = 0; k0 < D_; k0 += 8) {
        float4 av = Aptr ? *(const float4*)(Aptr + k0) : make_float4(0.f,0.f,0.f,0.f);
        As[ac4+0][arow] = av.x; As[ac4+1][arow] = av.y;
        As[ac4+2][arow] = av.z; As[ac4+3][arow] = av.w;
        *(float4*)&Bs[brow][bc4] = *(const float4*)(Wptr + (size_t)k0 * F_);
        __syncthreads();
        #pragma unroll
        for (int kk = 0; kk < 8; kk++) {
            float ra[8], rb[8];
            #pragma unroll
            for (int i = 0; i < 8; i++) ra[i] = As[kk][tr*8+i];
            #pragma unroll
            for (int j = 0; j < 8; j++) rb[j] = Bs[kk][tc*8+j];
            #pragma unroll
            for (int i = 0; i < 8; i++) {
                #pragma unroll
                for (int j = 0; j < 8; j++) acc[i][j] += ra[i] * rb[j];
            }
        }
        __syncthreads();
    }
    #pragma unroll
    for (int i = 0; i < 8; i++) {
        int row = tileM + tr*8 + i;
        int tok = g_slot_tok[row];
        if (tok < 0) continue;
        float* hrow = g_h + (size_t)row * F_ + tileN;
        #pragma unroll
        for (int j = 0; j < 8; j++) {
            float z = acc[i][j] + bias[tileN + tc*8 + j];
            hrow[tc*8+j] = gelu_f(z);
        }
    }
}

// ------------------------- expert FFN layer 2: macc[tok] += w * (h @ eW2[e] + eb2[e]) -------------------------
__global__ void __launch_bounds__(256) k_expert_ffn2(
    const float* __restrict__ eW2, const float* __restrict__ eb2)
{
    __shared__ float As[8][128];
    __shared__ float Bs[8][128];
    const int tid   = threadIdx.x;
    const int tileN = blockIdx.x * 128;
    const int tileM = blockIdx.y * 128;
    if (tileM >= g_offs[E_]) return;
    int e = 0;
    #pragma unroll
    for (int i = 1; i < E_; i++) if (tileM >= g_offs[i]) e = i;
    const float* W    = eW2 + (size_t)e * F_ * D_;
    const float* bias = eb2 + (size_t)e * D_;

    const int tr = tid >> 4, tc = tid & 15;
    const int arow = tid >> 1, ac4 = (tid & 1) * 4;
    const int brow = tid >> 5, bc4 = (tid & 31) * 4;

    const float* Aptr = g_h + (size_t)(tileM + arow) * F_ + ac4;
    const float* Wptr = W + (size_t)brow * D_ + tileN + bc4;

    float acc[8][8];
    #pragma unroll
    for (int i = 0; i < 8; i++) {
        #pragma unroll
        for (int j = 0; j < 8; j++) acc[i][j] = 0.f;
    }
    for (int k0 = 0; k0 < F_; k0 += 8) {
        float4 av = *(const float4*)(Aptr + k0);
        As[ac4+0][arow] = av.x; As[ac4+1][arow] = av.y;
        As[ac4+2][arow] = av.z; As[ac4+3][arow] = av.w;
        *(float4*)&Bs[brow][bc4] = *(const float4*)(Wptr + (size_t)k0 * D_);
        __syncthreads();
        #pragma unroll
        for (int kk = 0; kk < 8; kk++) {
            float ra[8], rb[8];
            #pragma unroll
            for (int i = 0; i < 8; i++) ra[i] = As[kk][tr*8+i];
            #pragma unroll
            for (int j = 0; j < 8; j++) rb[j] = Bs[kk][tc*8+j];
            #pragma unroll
            for (int i = 0; i < 8; i++) {
                #pragma unroll
                for (int j = 0; j < 8; j++) acc[i][j] += ra[i] * rb[j];
            }
        }
        __syncthreads();
    }
    #pragma unroll
    for (int i = 0; i < 8; i++) {
        int row = tileM + tr*8 + i;
        int tok = g_slot_tok[row];
        if (tok < 0) continue;
        float w = g_slot_w[row];
        float* mrow = g_macc + (size_t)tok * D_ + tileN;
        #pragma unroll
        for (int j = 0; j < 8; j++) {
            float z = acc[i][j] + bias[tileN + tc*8 + j];
            atomicAdd(&mrow[tc*8+j], w * z);
        }
    }
}

// ------------------------- aux loss -------------------------
__global__ void k_aux(float* __restrict__ out) {
    if (threadIdx.x == 0 && blockIdx.x == 0) {
        float a = 0.f;
        for (int e = 0; e < E_; e++)
            a += ((float)g_cnt[e] / (float)(T_ * TOPK_)) * (g_rsum[e] / (float)T_);
        out[0] = (float)E_ * a;
    }
}

// ------------------------- launch -------------------------
extern "C" void kernel_launch(void* const* d_in, const int* in_sizes, int n_in,
                              void* d_out, int out_size)
{
    const float* x     = (const float*)d_in[0];
    const float* Wq    = (const float*)d_in[1];
    const float* bq    = (const float*)d_in[2];
    const float* Wk    = (const float*)d_in[3];
    const float* bk    = (const float*)d_in[4];
    const float* Wv    = (const float*)d_in[5];
    const float* bv    = (const float*)d_in[6];
    const float* Wo    = (const float*)d_in[7];
    const float* bo    = (const float*)d_in[8];
    const float* g1    = (const float*)d_in[9];
    const float* beta1 = (const float*)d_in[10];
    const float* gateW = (const float*)d_in[11];
    const float* gateb = (const float*)d_in[12];
    const float* eW1   = (const float*)d_in[13];
    const float* eb1   = (const float*)d_in[14];
    const float* eW2   = (const float*)d_in[15];
    const float* eb2   = (const float*)d_in[16];
    const float* g2    = (const float*)d_in[17];
    const float* beta2 = (const float*)d_in[18];
    float* out = (float*)d_out;

    float *pq, *pk, *pv, *pattn, *pproj, *px1, *pmacc;
    cudaGetSymbolAddress((void**)&pq,    g_q);
    cudaGetSymbolAddress((void**)&pk,    g_k);
    cudaGetSymbolAddress((void**)&pv,    g_v);
    cudaGetSymbolAddress((void**)&pattn, g_attn);
    cudaGetSymbolAddress((void**)&pproj, g_proj);
    cudaGetSymbolAddress((void**)&px1,   g_x1);
    cudaGetSymbolAddress((void**)&pmacc, g_macc);

    const int FLASH_SMEM = (4*64*65 + 3*64) * sizeof(float);   // 67328 B
    cudaFuncSetAttribute(k_flash, cudaFuncAttributeMaxDynamicSharedMemorySize, FLASH_SMEM);

    // --- attention block ---
    dim3 gproj(D_/128, T_/128);
    k_gemm_bias<<<gproj, 256>>>(x, Wq, bq, pq, T_, D_, D_);
    k_gemm_bias<<<gproj, 256>>>(x, Wk, bk, pk, T_, D_, D_);
    k_gemm_bias<<<gproj, 256>>>(x, Wv, bv, pv, T_, D_, D_);
    k_flash<<<dim3(S_/64, H_, B_), 256, FLASH_SMEM>>>(pq, pk, pv, pattn);
    k_gemm_bias<<<gproj, 256>>>(pattn, Wo, bo, pproj, T_, D_, D_);
    k_add_ln<<<T_, 256>>>(x, pproj, g1, beta1, px1, 1);

    // --- MoE routing ---
    k_init_small<<<1, 32>>>();
    k_init_slots<<<(NSLOT_ + 255)/256, 256>>>();
    k_routing<<<T_/8, 256>>>(gateW, gateb);
    k_scan<<<1, 1>>>();
    k_fill_slots<<<(T_*TOPK_ + 255)/256, 256>>>();
    k_copy_macc<<<(T_*D_)/256, 256>>>();

    // --- expert FFN (sparse top-2, 128-padded segments) ---
    k_expert_ffn1<<<dim3(F_/128, NSLOT_/128), 256>>>(eW1, eb1);
    k_expert_ffn2<<<dim3(D_/128, NSLOT_/128), 256>>>(eW2, eb2);

    // --- final layernorm + aux loss ---
    k_add_ln<<<T_, 256>>>(pmacc, pmacc, g2, beta2, out, 0);
    if (out_size > T_*D_) k_aux<<<1, 1>>>(out + (size_t)T_*D_);
}

// round 4
// speedup vs baseline: 2.4501x; 2.4501x over previous
#include <cuda_runtime.h>
#include <math.h>
#include <stdint.h>

#define B_ 4
#define S_ 2048
#define D_ 1024
#define H_ 16
#define HD_ 64
#define F_ 4096
#define E_ 8
#define TOPK_ 2
#define T_ (B_*S_)                    // 8192 tokens
#define NSLOT_ (T_*TOPK_ + E_*128)    // 17408 padded expert slots

// ------------------------- static device scratch -------------------------
__device__ __align__(16) float g_q   [(size_t)T_*D_];
__device__ __align__(16) float g_kT  [(size_t)T_*D_];
__device__ __align__(16) float g_v   [(size_t)T_*D_];
__device__ __align__(16) float g_attn[(size_t)T_*D_];
__device__ __align__(16) float g_proj[(size_t)T_*D_];
__device__ __align__(16) float g_x1  [(size_t)T_*D_];
__device__ __align__(16) float g_macc[(size_t)T_*D_];
__device__ __align__(16) float g_h   [(size_t)NSLOT_*F_];
__device__ int   g_slot_tok[NSLOT_];
__device__ float g_slot_w[NSLOT_];
__device__ int   g_texp[T_*TOPK_];
__device__ int   g_tpos[T_*TOPK_];
__device__ float g_tw[T_*TOPK_];
__device__ int   g_cnt[E_];
__device__ float g_rsum[E_];
__device__ int   g_offs[E_+1];

// ------------------------- helpers -------------------------
__device__ __forceinline__ uint32_t tf32u(float x) {
    uint32_t u;
    asm("cvt.rna.tf32.f32 %0, %1;" : "=r"(u) : "f"(x));
    return u;
}
// split fp32 into tf32 hi + tf32 lo (3xTF32 scheme)
__device__ __forceinline__ void split2(float x, uint32_t& h, uint32_t& l) {
    h = tf32u(x);
    l = tf32u(x - __uint_as_float(h));
}
__device__ __forceinline__ void mma_tf32(float* d, const uint32_t* a, uint32_t b0, uint32_t b1) {
    asm volatile(
        "mma.sync.aligned.m16n8k8.row.col.f32.tf32.tf32.f32 "
        "{%0,%1,%2,%3}, {%4,%5,%6,%7}, {%8,%9}, {%0,%1,%2,%3};\n"
        : "+f"(d[0]), "+f"(d[1]), "+f"(d[2]), "+f"(d[3])
        : "r"(a[0]), "r"(a[1]), "r"(a[2]), "r"(a[3]), "r"(b0), "r"(b1));
}
__device__ __forceinline__ void cp16(void* dst, const void* src, bool p) {
    unsigned sa = (unsigned)__cvta_generic_to_shared(dst);
    int n = p ? 16 : 0;
    asm volatile("cp.async.cg.shared.global [%0], [%1], 16, %2;\n" :: "r"(sa), "l"(src), "r"(n));
}
__device__ __forceinline__ float gelu_f(float z) {
    return 0.5f * z * (1.0f + erff(z * 0.70710678118654752f));
}
// fast exp2 via degree-5 poly on fma pipe (avoids MUFU floor)
__device__ __forceinline__ float exp2_fast(float x) {
    x = fmaxf(x, -120.0f);
    int   n = __float2int_rn(x);
    float f = x - (float)n;
    float p = 1.33336498e-3f;
    p = fmaf(p, f, 9.61793571e-3f);
    p = fmaf(p, f, 5.55041087e-2f);
    p = fmaf(p, f, 2.40226507e-1f);
    p = fmaf(p, f, 6.93147181e-1f);
    p = fmaf(p, f, 1.0f);
    return __uint_as_float(__float_as_uint(p) + ((unsigned)n << 23));
}

// ------------------------- tensor-core GEMM (3xTF32) -------------------------
// C = A[M,Kd] @ W[Kd,N] + bias ; fp32 operands, split to tf32 hi/lo at fragment load.
// MODE 0: plain fp32 store.  1: store v*oscale.  2: K-transposed store.
// MODE 3: FFN1 (A gathered by slot_tok, gelu epilogue).  4: FFN2 (weighted atomicAdd scatter).
#define KT_ 32
#define AS_ST (128*36)
#define BS_ST (32*136)

template<int MODE>
__global__ void __launch_bounds__(256, 2) k_gemm_tc(
    const float* __restrict__ A, const float* __restrict__ W,
    const float* __restrict__ bias, float* __restrict__ C,
    int M, int N, int Kd, float oscale)
{
    extern __shared__ float sgm[];
    float* As = sgm;                 // 2 stages * 128*36
    float* Bs = sgm + 2*AS_ST;       // 2 stages * 32*136

    const int tid   = threadIdx.x;
    const int tileN = blockIdx.x * 128;
    const int tileM = blockIdx.y * 128;

    if (MODE == 3 || MODE == 4) {
        if (tileM >= g_offs[E_]) return;
        int expert = 0;
        #pragma unroll
        for (int i = 1; i < E_; i++) if (tileM >= g_offs[i]) expert = i;
        W    += (size_t)expert * Kd * N;
        bias += (size_t)expert * N;
    }

    // A loader setup (4 chunks / thread / stage)
    const float* aptr[4];
    bool apred[4];
    #pragma unroll
    for (int it = 0; it < 4; it++) {
        int r = (tid >> 3) + it * 32;
        int k4 = (tid & 7) * 4;
        int grow = tileM + r;
        if (MODE == 3) {
            int tok = g_slot_tok[grow];
            apred[it] = tok >= 0;
            aptr[it] = A + (size_t)(tok < 0 ? 0 : tok) * Kd + k4;
        } else {
            apred[it] = true;
            aptr[it] = A + (size_t)grow * Kd + k4;
        }
    }

    const int lane = tid & 31;
    const int g = lane >> 2, tq = lane & 3;
    const int wid = tid >> 5, wm = wid & 3, wn = wid >> 2;
    const int KTILES = Kd / KT_;

    float acc[2][8][4];
    #pragma unroll
    for (int mi = 0; mi < 2; mi++)
        #pragma unroll
        for (int n = 0; n < 8; n++)
            #pragma unroll
            for (int c = 0; c < 4; c++) acc[mi][n][c] = 0.f;

    auto load_stage = [&](int kt, int s) {
        #pragma unroll
        for (int it = 0; it < 4; it++) {
            const float* src = aptr[it] + (size_t)kt * KT_;
            float* dst = As + s*AS_ST + ((tid >> 3) + it*32) * 36 + (tid & 7) * 4;
            cp16(dst, src, apred[it]);
        }
        #pragma unroll
        for (int it = 0; it < 4; it++) {
            const float* src = W + (size_t)(kt*KT_ + (tid >> 5) + it*8) * N + tileN + (tid & 31) * 4;
            float* dst = Bs + s*BS_ST + ((tid >> 5) + it*8) * 136 + (tid & 31) * 4;
            cp16(dst, src, true);
        }
        asm volatile("cp.async.commit_group;\n");
    };

    load_stage(0, 0);
    for (int kt = 0; kt < KTILES; kt++) {
        if (kt + 1 < KTILES) {
            load_stage(kt + 1, (kt + 1) & 1);
            asm volatile("cp.async.wait_group 1;\n");
        } else {
            asm volatile("cp.async.wait_group 0;\n");
        }
        __syncthreads();
        const float* as = As + (kt & 1) * AS_ST;
        const float* bs = Bs + (kt & 1) * BS_ST;
        #pragma unroll
        for (int t = 0; t < 4; t++) {
            int k0 = t * 8;
            uint32_t ah[2][4], al[2][4];
            #pragma unroll
            for (int mi = 0; mi < 2; mi++) {
                int mrow = wm*32 + mi*16;
                split2(as[(mrow + g    ) * 36 + k0 + tq],     ah[mi][0], al[mi][0]);
                split2(as[(mrow + g + 8) * 36 + k0 + tq],     ah[mi][1], al[mi][1]);
                split2(as[(mrow + g    ) * 36 + k0 + tq + 4], ah[mi][2], al[mi][2]);
                split2(as[(mrow + g + 8) * 36 + k0 + tq + 4], ah[mi][3], al[mi][3]);
            }
            #pragma unroll
            for (int n = 0; n < 8; n++) {
                uint32_t bh0, bl0, bh1, bl1;
                split2(bs[(k0 + tq    ) * 136 + wn*64 + n*8 + g], bh0, bl0);
                split2(bs[(k0 + tq + 4) * 136 + wn*64 + n*8 + g], bh1, bl1);
                #pragma unroll
                for (int mi = 0; mi < 2; mi++) {
                    mma_tf32(acc[mi][n], ah[mi], bh0, bh1);
                    mma_tf32(acc[mi][n], al[mi], bh0, bh1);
                    mma_tf32(acc[mi][n], ah[mi], bl0, bl1);
                }
            }
        }
        __syncthreads();
    }

    // epilogue
    #pragma unroll
    for (int mi = 0; mi < 2; mi++) {
        #pragma unroll
        for (int rr = 0; rr < 2; rr++) {
            int row = tileM + wm*32 + mi*16 + g + rr*8;
            int tok = 0; float wgt = 0.f;
            if (MODE == 4) { tok = g_slot_tok[row]; wgt = g_slot_w[row]; }
            #pragma unroll
            for (int n = 0; n < 8; n++) {
                int col = tileN + wn*64 + n*8 + 2*tq;
                float v0 = acc[mi][n][rr*2 + 0] + bias[col];
                float v1 = acc[mi][n][rr*2 + 1] + bias[col + 1];
                if (MODE == 0) {
                    *(float2*)&C[(size_t)row * N + col] = make_float2(v0, v1);
                } else if (MODE == 1) {
                    *(float2*)&C[(size_t)row * N + col] =
                        make_float2(v0 * oscale, v1 * oscale);
                } else if (MODE == 2) {
                    int b = row >> 11, st = row & 2047;
                    int h0 = col >> 6, hd0 = col & 63;
                    int h1 = (col+1) >> 6, hd1 = (col+1) & 63;
                    C[(size_t)(((b*H_ + h0)*64 + hd0)) * S_ + st] = v0;
                    C[(size_t)(((b*H_ + h1)*64 + hd1)) * S_ + st] = v1;
                } else if (MODE == 3) {
                    *(float2*)&C[(size_t)row * N + col] =
                        make_float2(gelu_f(v0), gelu_f(v1));
                } else { // MODE 4
                    if (tok >= 0) {
                        atomicAdd(&C[(size_t)tok * N + col],     wgt * v0);
                        atomicAdd(&C[(size_t)tok * N + col + 1], wgt * v1);
                    }
                }
            }
        }
    }
}

// ------------------------- tensor-core flash attention (3xTF32) -------------------------
// q pre-scaled by (1/8)*log2(e). kT layout [B][H][64][S]. v natural. All fp32 in SMEM.
__global__ void __launch_bounds__(128, 2) k_flash_tc(
    const float* __restrict__ q, const float* __restrict__ kT,
    const float* __restrict__ v, float* __restrict__ o)
{
    extern __shared__ float sgm[];
    float* Ks = sgm;             // 64 x 72
    float* Vs = sgm + 64*72;     // 64 x 72
    float* Ps = sgm + 2*64*72;   // 64 x 68

    const int tid  = threadIdx.x;
    const int lane = tid & 31, wid = tid >> 5;
    const int g = lane >> 2, tq = lane & 3;
    const int q0 = blockIdx.x * 64, h = blockIdx.y, b = blockIdx.z;
    const size_t tokbase = (size_t)b * S_ + q0 + wid * 16;

    // Q fragments: rows wid*16 + {g, g+8}, full HD=64, pre-split hi/lo
    uint32_t qh[8][4], ql[8][4];
    const float* qb = q + tokbase * D_ + h * 64;
    #pragma unroll
    for (int t = 0; t < 8; t++) {
        split2(qb[(size_t)(g    ) * D_ + t*8 + tq],     qh[t][0], ql[t][0]);
        split2(qb[(size_t)(g + 8) * D_ + t*8 + tq],     qh[t][1], ql[t][1]);
        split2(qb[(size_t)(g    ) * D_ + t*8 + tq + 4], qh[t][2], ql[t][2]);
        split2(qb[(size_t)(g + 8) * D_ + t*8 + tq + 4], qh[t][3], ql[t][3]);
    }
    const float* kbase = kT + ((size_t)(b*H_ + h) * 64) * S_;   // [hd][S]
    const float* vbase = v + ((size_t)b * S_) * D_ + h * 64;    // [token][D] slice

    float oc[8][4];
    #pragma unroll
    for (int n = 0; n < 8; n++)
        #pragma unroll
        for (int c = 0; c < 4; c++) oc[n][c] = 0.f;
    float mr[2] = {-1e30f, -1e30f}, lr[2] = {0.f, 0.f};

    for (int kt = 0; kt < S_; kt += 64) {
        #pragma unroll
        for (int it = 0; it < 8; it++) {
            int id = tid + it * 128;
            int r = id >> 4, c4 = (id & 15) * 4;
            *(float4*)&Ks[r*72 + c4] = *(const float4*)&kbase[(size_t)r * S_ + kt + c4];
            *(float4*)&Vs[r*72 + c4] = *(const float4*)&vbase[(size_t)(kt + r) * D_ + c4];
        }
        __syncthreads();

        // S = Q K^T (log2 domain via Q pre-scale), 3xTF32
        float sacc[8][4];
        #pragma unroll
        for (int n = 0; n < 8; n++)
            #pragma unroll
            for (int c = 0; c < 4; c++) sacc[n][c] = 0.f;
        #pragma unroll
        for (int t = 0; t < 8; t++) {
            #pragma unroll
            for (int n = 0; n < 8; n++) {
                uint32_t bh0, bl0, bh1, bl1;
                split2(Ks[(t*8 + tq    ) * 72 + n*8 + g], bh0, bl0);
                split2(Ks[(t*8 + tq + 4) * 72 + n*8 + g], bh1, bl1);
                mma_tf32(sacc[n], qh[t], bh0, bh1);
                mma_tf32(sacc[n], ql[t], bh0, bh1);
                mma_tf32(sacc[n], qh[t], bl0, bl1);
            }
        }

        // online softmax
        float rmax[2] = {-1e30f, -1e30f};
        #pragma unroll
        for (int n = 0; n < 8; n++) {
            rmax[0] = fmaxf(rmax[0], fmaxf(sacc[n][0], sacc[n][1]));
            rmax[1] = fmaxf(rmax[1], fmaxf(sacc[n][2], sacc[n][3]));
        }
        #pragma unroll
        for (int off = 1; off <= 2; off <<= 1) {
            rmax[0] = fmaxf(rmax[0], __shfl_xor_sync(0xffffffffu, rmax[0], off));
            rmax[1] = fmaxf(rmax[1], __shfl_xor_sync(0xffffffffu, rmax[1], off));
        }
        float mnew[2] = { fmaxf(mr[0], rmax[0]), fmaxf(mr[1], rmax[1]) };
        float alpha[2] = { exp2_fast(mr[0] - mnew[0]), exp2_fast(mr[1] - mnew[1]) };
        float lsum[2] = {0.f, 0.f};
        const int prow = wid * 16;
        #pragma unroll
        for (int n = 0; n < 8; n++) {
            float p00 = exp2_fast(sacc[n][0] - mnew[0]);
            float p01 = exp2_fast(sacc[n][1] - mnew[0]);
            float p10 = exp2_fast(sacc[n][2] - mnew[1]);
            float p11 = exp2_fast(sacc[n][3] - mnew[1]);
            lsum[0] += p00 + p01;
            lsum[1] += p10 + p11;
            *(float2*)&Ps[(prow + g    ) * 68 + n*8 + 2*tq] = make_float2(p00, p01);
            *(float2*)&Ps[(prow + g + 8) * 68 + n*8 + 2*tq] = make_float2(p10, p11);
        }
        #pragma unroll
        for (int off = 1; off <= 2; off <<= 1) {
            lsum[0] += __shfl_xor_sync(0xffffffffu, lsum[0], off);
            lsum[1] += __shfl_xor_sync(0xffffffffu, lsum[1], off);
        }
        lr[0] = lr[0] * alpha[0] + lsum[0];
        lr[1] = lr[1] * alpha[1] + lsum[1];
        mr[0] = mnew[0]; mr[1] = mnew[1];
        #pragma unroll
        for (int n = 0; n < 8; n++) {
            oc[n][0] *= alpha[0]; oc[n][1] *= alpha[0];
            oc[n][2] *= alpha[1]; oc[n][3] *= alpha[1];
        }
        __syncwarp();

        // O += P V, 3xTF32 (P split too)
        #pragma unroll
        for (int t = 0; t < 8; t++) {
            uint32_t pah[4], pal[4];
            split2(Ps[(prow + g    ) * 68 + t*8 + tq],     pah[0], pal[0]);
            split2(Ps[(prow + g + 8) * 68 + t*8 + tq],     pah[1], pal[1]);
            split2(Ps[(prow + g    ) * 68 + t*8 + tq + 4], pah[2], pal[2]);
            split2(Ps[(prow + g + 8) * 68 + t*8 + tq + 4], pah[3], pal[3]);
            #pragma unroll
            for (int n = 0; n < 8; n++) {
                uint32_t bh0, bl0, bh1, bl1;
                split2(Vs[(t*8 + tq    ) * 72 + n*8 + g], bh0, bl0);
                split2(Vs[(t*8 + tq + 4) * 72 + n*8 + g], bh1, bl1);
                mma_tf32(oc[n], pah, bh0, bh1);
                mma_tf32(oc[n], pal, bh0, bh1);
                mma_tf32(oc[n], pah, bl0, bl1);
            }
        }
        __syncthreads();
    }

    float inv0 = 1.f / lr[0], inv1 = 1.f / lr[1];
    float* ob = o + tokbase * D_ + h * 64;
    #pragma unroll
    for (int n = 0; n < 8; n++) {
        int col = n*8 + 2*tq;
        *(float2*)&ob[(size_t)(g    ) * D_ + col] =
            make_float2(oc[n][0] * inv0, oc[n][1] * inv0);
        *(float2*)&ob[(size_t)(g + 8) * D_ + col] =
            make_float2(oc[n][2] * inv1, oc[n][3] * inv1);
    }
}

// ------------------------- residual + layernorm -------------------------
__global__ void __launch_bounds__(256) k_add_ln(
    const float* __restrict__ x, const float* __restrict__ r,
    const float* __restrict__ g, const float* __restrict__ be,
    float* __restrict__ out, int has_r)
{
    __shared__ float red[8];
    __shared__ float s_mu, s_inv;
    const int t = blockIdx.x;
    const int tid = threadIdx.x;
    const float* xr = x + (size_t)t * D_;
    const float* rr = r + (size_t)t * D_;

    float v[4];
    float s = 0.f;
    #pragma unroll
    for (int i = 0; i < 4; i++) {
        int idx = tid + i * 256;
        v[i] = xr[idx] + (has_r ? rr[idx] : 0.f);
        s += v[i];
    }
    #pragma unroll
    for (int o = 16; o > 0; o >>= 1) s += __shfl_down_sync(0xffffffffu, s, o);
    if ((tid & 31) == 0) red[tid >> 5] = s;
    __syncthreads();
    if (tid < 8) {
        s = red[tid];
        #pragma unroll
        for (int o = 4; o > 0; o >>= 1) s += __shfl_down_sync(0xffu, s, o);
        if (tid == 0) s_mu = s * (1.f / D_);
    }
    __syncthreads();
    const float mu = s_mu;
    float sq = 0.f;
    #pragma unroll
    for (int i = 0; i < 4; i++) { float d = v[i] - mu; sq += d * d; }
    #pragma unroll
    for (int o = 16; o > 0; o >>= 1) sq += __shfl_down_sync(0xffffffffu, sq, o);
    __syncthreads();
    if ((tid & 31) == 0) red[tid >> 5] = sq;
    __syncthreads();
    if (tid < 8) {
        sq = red[tid];
        #pragma unroll
        for (int o = 4; o > 0; o >>= 1) sq += __shfl_down_sync(0xffu, sq, o);
        if (tid == 0) s_inv = rsqrtf(sq * (1.f / D_) + 1e-5f);
    }
    __syncthreads();
    const float inv = s_inv;
    #pragma unroll
    for (int i = 0; i < 4; i++) {
        int idx = tid + i * 256;
        out[(size_t)t * D_ + idx] = (v[i] - mu) * inv * g[idx] + be[idx];
    }
}

// ------------------------- MoE routing -------------------------
__global__ void k_init_small() {
    int i = threadIdx.x;
    if (i < E_) { g_cnt[i] = 0; g_rsum[i] = 0.f; }
}
__global__ void k_init_slots() {
    int i = blockIdx.x * 256 + threadIdx.x;
    if (i < NSLOT_) g_slot_tok[i] = -1;
}
__global__ void k_copy_macc() {
    size_t i = (size_t)blockIdx.x * 256 + threadIdx.x;
    g_macc[i] = g_x1[i];
}

__global__ void __launch_bounds__(256) k_routing(
    const float* __restrict__ gateW, const float* __restrict__ gateb)
{
    const int gtid = blockIdx.x * blockDim.x + threadIdx.x;
    const int t = gtid >> 5;
    const int lane = gtid & 31;
    if (t >= T_) return;
    const float* xr = g_x1 + (size_t)t * D_;
    float acc[E_];
    #pragma unroll
    for (int e = 0; e < E_; e++) acc[e] = 0.f;
    for (int d = lane; d < D_; d += 32) {
        float xv = xr[d];
        const float* gw = gateW + (size_t)d * E_;
        #pragma unroll
        for (int e = 0; e < E_; e++) acc[e] += xv * gw[e];
    }
    #pragma unroll
    for (int e = 0; e < E_; e++) {
        #pragma unroll
        for (int o = 16; o > 0; o >>= 1)
            acc[e] += __shfl_down_sync(0xffffffffu, acc[e], o);
    }
    if (lane == 0) {
        float p[E_];
        float mx = -1e30f;
        #pragma unroll
        for (int e = 0; e < E_; e++) { acc[e] += gateb[e]; mx = fmaxf(mx, acc[e]); }
        float ssum = 0.f;
        #pragma unroll
        for (int e = 0; e < E_; e++) { p[e] = expf(acc[e] - mx); ssum += p[e]; }
        float invs = 1.f / ssum;
        #pragma unroll
        for (int e = 0; e < E_; e++) { p[e] *= invs; atomicAdd(&g_rsum[e], p[e]); }
        int i0 = 0;
        #pragma unroll
        for (int e = 1; e < E_; e++) if (p[e] > p[i0]) i0 = e;
        int i1 = -1;
        #pragma unroll
        for (int e = 0; e < E_; e++)
            if (e != i0 && (i1 < 0 || p[e] > p[i1])) i1 = e;
        float wsum = p[i0] + p[i1];
        int pos0 = atomicAdd(&g_cnt[i0], 1);
        int pos1 = atomicAdd(&g_cnt[i1], 1);
        g_texp[2*t]   = i0; g_tpos[2*t]   = pos0; g_tw[2*t]   = p[i0] / wsum;
        g_texp[2*t+1] = i1; g_tpos[2*t+1] = pos1; g_tw[2*t+1] = p[i1] / wsum;
    }
}

__global__ void k_scan() {
    if (threadIdx.x == 0 && blockIdx.x == 0) {
        int o = 0;
        for (int e = 0; e < E_; e++) {
            g_offs[e] = o;
            o += ((g_cnt[e] + 127) >> 7) << 7;
        }
        g_offs[E_] = o;
    }
}

__global__ void k_fill_slots() {
    int i = blockIdx.x * 256 + threadIdx.x;
    if (i >= T_ * TOPK_) return;
    int e = g_texp[i];
    int slot = g_offs[e] + g_tpos[i];
    g_slot_tok[slot] = i >> 1;
    g_slot_w[slot] = g_tw[i];
}

__global__ void k_aux(float* __restrict__ out) {
    if (threadIdx.x == 0 && blockIdx.x == 0) {
        float a = 0.f;
        for (int e = 0; e < E_; e++)
            a += ((float)g_cnt[e] / (float)(T_ * TOPK_)) * (g_rsum[e] / (float)T_);
        out[0] = (float)E_ * a;
    }
}

// ------------------------- launch -------------------------
extern "C" void kernel_launch(void* const* d_in, const int* in_sizes, int n_in,
                              void* d_out, int out_size)
{
    const float* x     = (const float*)d_in[0];
    const float* Wq    = (const float*)d_in[1];
    const float* bq    = (const float*)d_in[2];
    const float* Wk    = (const float*)d_in[3];
    const float* bk    = (const float*)d_in[4];
    const float* Wv    = (const float*)d_in[5];
    const float* bv    = (const float*)d_in[6];
    const float* Wo    = (const float*)d_in[7];
    const float* bo    = (const float*)d_in[8];
    const float* g1    = (const float*)d_in[9];
    const float* beta1 = (const float*)d_in[10];
    const float* gateW = (const float*)d_in[11];
    const float* gateb = (const float*)d_in[12];
    const float* eW1   = (const float*)d_in[13];
    const float* eb1   = (const float*)d_in[14];
    const float* eW2   = (const float*)d_in[15];
    const float* eb2   = (const float*)d_in[16];
    const float* g2    = (const float*)d_in[17];
    const float* beta2 = (const float*)d_in[18];
    float* out = (float*)d_out;

    float *pq, *pkT, *pv, *pattn, *pproj, *px1, *pmacc, *ph;
    cudaGetSymbolAddress((void**)&pq,    g_q);
    cudaGetSymbolAddress((void**)&pkT,   g_kT);
    cudaGetSymbolAddress((void**)&pv,    g_v);
    cudaGetSymbolAddress((void**)&pattn, g_attn);
    cudaGetSymbolAddress((void**)&pproj, g_proj);
    cudaGetSymbolAddress((void**)&px1,   g_x1);
    cudaGetSymbolAddress((void**)&pmacc, g_macc);
    cudaGetSymbolAddress((void**)&ph,    g_h);

    const int GEMM_SMEM = (2*AS_ST + 2*BS_ST) * 4;                 // 71680 B
    const int FLASH_SMEM = (2*64*72 + 64*68) * 4;                  // 54272 B
    cudaFuncSetAttribute(k_gemm_tc<0>, cudaFuncAttributeMaxDynamicSharedMemorySize, GEMM_SMEM);
    cudaFuncSetAttribute(k_gemm_tc<1>, cudaFuncAttributeMaxDynamicSharedMemorySize, GEMM_SMEM);
    cudaFuncSetAttribute(k_gemm_tc<2>, cudaFuncAttributeMaxDynamicSharedMemorySize, GEMM_SMEM);
    cudaFuncSetAttribute(k_gemm_tc<3>, cudaFuncAttributeMaxDynamicSharedMemorySize, GEMM_SMEM);
    cudaFuncSetAttribute(k_gemm_tc<4>, cudaFuncAttributeMaxDynamicSharedMemorySize, GEMM_SMEM);
    cudaFuncSetAttribute(k_flash_tc,   cudaFuncAttributeMaxDynamicSharedMemorySize, FLASH_SMEM);

    // --- attention block ---
    const float QSCALE = 0.125f * 1.4426950408889634f;   // 1/sqrt(HD) * log2(e)
    dim3 gproj(D_/128, T_/128);
    k_gemm_tc<1><<<gproj, 256, GEMM_SMEM>>>(x, Wq, bq, pq,  T_, D_, D_, QSCALE);
    k_gemm_tc<2><<<gproj, 256, GEMM_SMEM>>>(x, Wk, bk, pkT, T_, D_, D_, 1.f);
    k_gemm_tc<0><<<gproj, 256, GEMM_SMEM>>>(x, Wv, bv, pv,  T_, D_, D_, 1.f);
    k_flash_tc<<<dim3(S_/64, H_, B_), 128, FLASH_SMEM>>>(pq, pkT, pv, pattn);
    k_gemm_tc<0><<<gproj, 256, GEMM_SMEM>>>(pattn, Wo, bo, pproj, T_, D_, D_, 1.f);
    k_add_ln<<<T_, 256>>>(x, pproj, g1, beta1, px1, 1);

    // --- MoE routing ---
    k_init_small<<<1, 32>>>();
    k_init_slots<<<(NSLOT_ + 255)/256, 256>>>();
    k_routing<<<T_/8, 256>>>(gateW, gateb);
    k_scan<<<1, 1>>>();
    k_fill_slots<<<(T_*TOPK_ + 255)/256, 256>>>();
    k_copy_macc<<<(T_*D_)/256, 256>>>();

    // --- expert FFN (sparse top-2, 128-padded segments, 3xTF32) ---
    k_gemm_tc<3><<<dim3(F_/128, NSLOT_/128), 256, GEMM_SMEM>>>(px1, eW1, eb1, ph,    NSLOT_, F_, D_, 1.f);
    k_gemm_tc<4><<<dim3(D_/128, NSLOT_/128), 256, GEMM_SMEM>>>(ph,  eW2, eb2, pmacc, NSLOT_, D_, F_, 1.f);

    // --- final layernorm + aux loss ---
    k_add_ln<<<T_, 256>>>(pmacc, pmacc, g2, beta2, out, 0);
    if (out_size > T_*D_) k_aux<<<1, 1>>>(out + (size_t)T_*D_);
}

// round 7
// speedup vs baseline: 4.4489x; 1.8158x over previous
#include <cuda_runtime.h>
#include <cuda_bf16.h>
#include <math.h>
#include <stdint.h>

#define B_ 4
#define S_ 2048
#define D_ 1024
#define H_ 16
#define HD_ 64
#define F_ 4096
#define E_ 8
#define TOPK_ 2
#define T_ (B_*S_)                    // 8192 tokens
#define NSLOT_ (T_*TOPK_ + E_*128)    // 17408 padded expert slots

// ------------------------- static device scratch -------------------------
// bf16 hi/lo planes (hi+lo = same bytes as fp32)
__device__ __align__(16) __nv_bfloat16 g_xhi [(size_t)T_*D_];
__device__ __align__(16) __nv_bfloat16 g_xlo [(size_t)T_*D_];
__device__ __align__(16) __nv_bfloat16 g_qhi [(size_t)T_*D_];
__device__ __align__(16) __nv_bfloat16 g_qlo [(size_t)T_*D_];
__device__ __align__(16) __nv_bfloat16 g_khi [(size_t)T_*D_];
__device__ __align__(16) __nv_bfloat16 g_klo [(size_t)T_*D_];
__device__ __align__(16) __nv_bfloat16 g_vthi[(size_t)T_*D_];   // [B][H][hd][S]
__device__ __align__(16) __nv_bfloat16 g_vtlo[(size_t)T_*D_];
__device__ __align__(16) __nv_bfloat16 g_athi[(size_t)T_*D_];
__device__ __align__(16) __nv_bfloat16 g_atlo[(size_t)T_*D_];
__device__ __align__(16) __nv_bfloat16 g_x1hi[(size_t)T_*D_];
__device__ __align__(16) __nv_bfloat16 g_x1lo[(size_t)T_*D_];
__device__ __align__(16) __nv_bfloat16 g_hhi [(size_t)NSLOT_*F_];
__device__ __align__(16) __nv_bfloat16 g_hlo [(size_t)NSLOT_*F_];
// weights: transposed [N,K] bf16 planes
__device__ __align__(16) __nv_bfloat16 g_Wqh[D_*D_], g_Wql[D_*D_];
__device__ __align__(16) __nv_bfloat16 g_Wkh[D_*D_], g_Wkl[D_*D_];
__device__ __align__(16) __nv_bfloat16 g_Wvh[D_*D_], g_Wvl[D_*D_];
__device__ __align__(16) __nv_bfloat16 g_Woh[D_*D_], g_Wol[D_*D_];
__device__ __align__(16) __nv_bfloat16 g_W1h[(size_t)E_*D_*F_], g_W1l[(size_t)E_*D_*F_];
__device__ __align__(16) __nv_bfloat16 g_W2h[(size_t)E_*F_*D_], g_W2l[(size_t)E_*F_*D_];
// fp32 buffers
__device__ __align__(16) float g_proj[(size_t)T_*D_];
__device__ __align__(16) float g_x1  [(size_t)T_*D_];
__device__ __align__(16) float g_macc[(size_t)T_*D_];
// routing
__device__ int   g_slot_tok[NSLOT_];
__device__ float g_slot_w[NSLOT_];
__device__ int   g_texp[T_*TOPK_];
__device__ int   g_tpos[T_*TOPK_];
__device__ float g_tw[T_*TOPK_];
__device__ int   g_cnt[E_];
__device__ float g_rsum[E_];
__device__ int   g_offs[E_+1];

// ------------------------- helpers -------------------------
// pack two fp32 -> bf16x2 (lo in low half, hi arg in high half)
__device__ __forceinline__ uint32_t pkbf(float lo, float hi) {
    uint32_t r;
    asm("cvt.rn.bf16x2.f32 %0, %1, %2;" : "=r"(r) : "f"(hi), "f"(lo));
    return r;
}
// split (v0,v1) into hi-plane word + lo-plane word (bf16x3 scheme)
__device__ __forceinline__ void split2u(float v0, float v1, uint32_t& h, uint32_t& l) {
    h = pkbf(v0, v1);
    float r0 = v0 - __uint_as_float(h << 16);
    float r1 = v1 - __uint_as_float(h & 0xffff0000u);
    l = pkbf(r0, r1);
}
__device__ __forceinline__ void mma_bf16(float* d, const uint32_t* a, uint32_t b0, uint32_t b1) {
    asm volatile(
        "mma.sync.aligned.m16n8k16.row.col.f32.bf16.bf16.f32 "
        "{%0,%1,%2,%3}, {%4,%5,%6,%7}, {%8,%9}, {%0,%1,%2,%3};\n"
        : "+f"(d[0]), "+f"(d[1]), "+f"(d[2]), "+f"(d[3])
        : "r"(a[0]), "r"(a[1]), "r"(a[2]), "r"(a[3]), "r"(b0), "r"(b1));
}
__device__ __forceinline__ void ldsm4(uint32_t* r, uint32_t saddr) {
    asm volatile("ldmatrix.sync.aligned.m8n8.x4.shared.b16 {%0,%1,%2,%3}, [%4];"
        : "=r"(r[0]), "=r"(r[1]), "=r"(r[2]), "=r"(r[3]) : "r"(saddr));
}
__device__ __forceinline__ void ldsm2(uint32_t* r, uint32_t saddr) {
    asm volatile("ldmatrix.sync.aligned.m8n8.x2.shared.b16 {%0,%1}, [%2];"
        : "=r"(r[0]), "=r"(r[1]) : "r"(saddr));
}
__device__ __forceinline__ void cp16(void* dst, const void* src, bool p) {
    unsigned sa = (unsigned)__cvta_generic_to_shared(dst);
    int n = p ? 16 : 0;
    asm volatile("cp.async.cg.shared.global [%0], [%1], 16, %2;\n" :: "r"(sa), "l"(src), "r"(n));
}
__device__ __forceinline__ float gelu_f(float z) {
    return 0.5f * z * (1.0f + erff(z * 0.70710678118654752f));
}
__device__ __forceinline__ float exp2_fast(float x) {
    x = fmaxf(x, -120.0f);
    int   n = __float2int_rn(x);
    float f = x - (float)n;
    float p = 1.33336498e-3f;
    p = fmaf(p, f, 9.61793571e-3f);
    p = fmaf(p, f, 5.55041087e-2f);
    p = fmaf(p, f, 2.40226507e-1f);
    p = fmaf(p, f, 6.93147181e-1f);
    p = fmaf(p, f, 1.0f);
    return __uint_as_float(__float_as_uint(p) + ((unsigned)n << 23));
}

// ------------------------- pre-pass: split activations -------------------------
__global__ void k_asplit(const float2* __restrict__ src,
                         __nv_bfloat16* __restrict__ hi, __nv_bfloat16* __restrict__ lo, int n2) {
    int i = blockIdx.x * 256 + threadIdx.x;
    if (i < n2) {
        float2 v = src[i];
        uint32_t h, l;
        split2u(v.x, v.y, h, l);
        ((uint32_t*)hi)[i] = h;
        ((uint32_t*)lo)[i] = l;
    }
}

// ------------------------- pre-pass: transpose + split weights -------------------------
// W [K,N] fp32 -> Whi/Wlo [N,K] bf16.  grid (N/32, K/32, batch), 256 threads.
__global__ void __launch_bounds__(256) k_wT(
    const float* __restrict__ W, __nv_bfloat16* __restrict__ Whi,
    __nv_bfloat16* __restrict__ Wlo, int K, int N)
{
    __shared__ float t[32][33];
    const size_t mat = (size_t)blockIdx.z * K * N;
    W += mat; Whi += mat; Wlo += mat;
    const int n0 = blockIdx.x * 32, k0 = blockIdx.y * 32;
    const int tid = threadIdx.x;
    #pragma unroll
    for (int i = 0; i < 4; i++) {
        int idx = tid + i * 256;
        int r = idx >> 5, c = idx & 31;
        t[r][c] = W[(size_t)(k0 + r) * N + n0 + c];
    }
    __syncthreads();
    #pragma unroll
    for (int i = 0; i < 2; i++) {
        int idx = tid + i * 256;          // 512 (n, k-pair) tasks
        int nr = idx >> 4, kp = idx & 15;
        float v0 = t[2*kp][nr], v1 = t[2*kp + 1][nr];
        uint32_t h, l;
        split2u(v0, v1, h, l);
        *(uint32_t*)&Whi[(size_t)(n0 + nr) * K + k0 + 2*kp] = h;
        *(uint32_t*)&Wlo[(size_t)(n0 + nr) * K + k0 + 2*kp] = l;
    }
}

// ------------------------- tensor-core GEMM (bf16x3) -------------------------
// C = A[M,Kd] @ W[Kd,N] + bias. A, W given as bf16 hi/lo planes; W transposed [N,Kd].
// MODE 0: fp32 store.  1: split-store planes (scaled).  2: V-transposed split planes.
// MODE 3: FFN1 (A gathered by slot_tok, gelu + split planes).  4: FFN2 (weighted atomicAdd).
#define KT_ 32
#define APL_ (128*40)       // bf16 per plane per stage
#define ASTG_ (2*APL_)      // hi+lo

template<int MODE>
__global__ void __launch_bounds__(256, 2) k_gemm_bf(
    const __nv_bfloat16* __restrict__ Ahi, const __nv_bfloat16* __restrict__ Alo,
    const __nv_bfloat16* __restrict__ Bhi, const __nv_bfloat16* __restrict__ Blo,
    const float* __restrict__ bias,
    float* __restrict__ C, __nv_bfloat16* __restrict__ Chi, __nv_bfloat16* __restrict__ Clo,
    int M, int N, int Kd, float oscale)
{
    extern __shared__ __nv_bfloat16 sgb[];
    __nv_bfloat16* As = sgb;                  // 2 stages x ASTG_
    __nv_bfloat16* Bs = sgb + 2*ASTG_;

    const int tid   = threadIdx.x;
    const int tileN = blockIdx.x * 128;
    const int tileM = blockIdx.y * 128;

    if (MODE == 3 || MODE == 4) {
        if (tileM >= g_offs[E_]) return;
        int expert = 0;
        #pragma unroll
        for (int i = 1; i < E_; i++) if (tileM >= g_offs[i]) expert = i;
        Bhi  += (size_t)expert * Kd * N;
        Blo  += (size_t)expert * Kd * N;
        bias += (size_t)expert * N;
    }

    // loader setup: 4 A chunks + 4 B chunks per thread per stage (16B each)
    const __nv_bfloat16* aptr[4];
    bool apred[4];
    int adst[4];
    const __nv_bfloat16* bptr[4];
    int bdst[4];
    #pragma unroll
    for (int it = 0; it < 4; it++) {
        int cid = tid + it * 256;          // 0..1023
        int p = cid >> 9, rem = cid & 511;
        int row = rem >> 2, c16 = rem & 3;
        // A
        int grow = tileM + row;
        const __nv_bfloat16* abase = p ? Alo : Ahi;
        if (MODE == 3) {
            int tok = g_slot_tok[grow];
            apred[it] = tok >= 0;
            aptr[it] = abase + (size_t)(tok < 0 ? 0 : tok) * Kd + c16 * 8;
        } else {
            apred[it] = true;
            aptr[it] = abase + (size_t)grow * Kd + c16 * 8;
        }
        adst[it] = p * APL_ + row * 40 + c16 * 8;
        // B
        const __nv_bfloat16* bbase = p ? Blo : Bhi;
        bptr[it] = bbase + (size_t)(tileN + row) * Kd + c16 * 8;
        bdst[it] = p * APL_ + row * 40 + c16 * 8;
    }

    const int lane = tid & 31;
    const int g = lane >> 2, tq = lane & 3;
    const int wid = tid >> 5, wm = wid & 3, wn = wid >> 2;
    const int KTILES = Kd / KT_;
    const uint32_t sbase = (uint32_t)__cvta_generic_to_shared(sgb);
    const uint32_t a_lsel = (lane & 15) * 80 + (lane >> 4) * 16;       // bytes
    const uint32_t b_lsel = (lane & 7) * 80 + ((lane >> 3) & 1) * 16;  // bytes

    float acc[2][8][4];
    #pragma unroll
    for (int mi = 0; mi < 2; mi++)
        #pragma unroll
        for (int n = 0; n < 8; n++)
            #pragma unroll
            for (int c = 0; c < 4; c++) acc[mi][n][c] = 0.f;

    auto load_stage = [&](int kt, int s) {
        #pragma unroll
        for (int it = 0; it < 4; it++)
            cp16(As + s*ASTG_ + adst[it], aptr[it] + (size_t)kt * KT_, apred[it]);
        #pragma unroll
        for (int it = 0; it < 4; it++)
            cp16(Bs + s*ASTG_ + bdst[it], bptr[it] + (size_t)kt * KT_, true);
        asm volatile("cp.async.commit_group;\n");
    };

    load_stage(0, 0);
    for (int kt = 0; kt < KTILES; kt++) {
        if (kt + 1 < KTILES) {
            load_stage(kt + 1, (kt + 1) & 1);
            asm volatile("cp.async.wait_group 1;\n");
        } else {
            asm volatile("cp.async.wait_group 0;\n");
        }
        __syncthreads();
        const uint32_t as0 = sbase + ((kt & 1) * ASTG_) * 2;
        const uint32_t bs0 = sbase + (2*ASTG_ + (kt & 1) * ASTG_) * 2;
        #pragma unroll
        for (int t = 0; t < 2; t++) {
            const uint32_t kb = t * 32;   // byte offset of k16 step within row
            uint32_t ah[2][4], al[2][4];
            #pragma unroll
            for (int mi = 0; mi < 2; mi++) {
                uint32_t ra = as0 + (uint32_t)(wm*32 + mi*16) * 80 + a_lsel + kb;
                ldsm4(ah[mi], ra);
                ldsm4(al[mi], ra + APL_*2);
            }
            #pragma unroll
            for (int n = 0; n < 8; n++) {
                uint32_t rb = bs0 + (uint32_t)(wn*64 + n*8) * 80 + b_lsel + kb;
                uint32_t bh[2], bl[2];
                ldsm2(bh, rb);
                ldsm2(bl, rb + APL_*2);
                #pragma unroll
                for (int mi = 0; mi < 2; mi++) {
                    mma_bf16(acc[mi][n], ah[mi], bh[0], bh[1]);
                    mma_bf16(acc[mi][n], al[mi], bh[0], bh[1]);
                    mma_bf16(acc[mi][n], ah[mi], bl[0], bl[1]);
                }
            }
        }
        __syncthreads();
    }

    // epilogue
    #pragma unroll
    for (int mi = 0; mi < 2; mi++) {
        #pragma unroll
        for (int rr = 0; rr < 2; rr++) {
            int row = tileM + wm*32 + mi*16 + g + rr*8;
            int tok = 0; float wgt = 0.f;
            if (MODE == 4) { tok = g_slot_tok[row]; wgt = g_slot_w[row]; }
            if (MODE == 3) { if (g_slot_tok[row] < 0) continue; }
            #pragma unroll
            for (int n = 0; n < 8; n++) {
                int col = tileN + wn*64 + n*8 + 2*tq;
                float v0 = acc[mi][n][rr*2 + 0] + bias[col];
                float v1 = acc[mi][n][rr*2 + 1] + bias[col + 1];
                if (MODE == 0) {
                    *(float2*)&C[(size_t)row * N + col] = make_float2(v0, v1);
                } else if (MODE == 1) {
                    uint32_t h, l;
                    split2u(v0 * oscale, v1 * oscale, h, l);
                    *(uint32_t*)&Chi[(size_t)row * N + col] = h;
                    *(uint32_t*)&Clo[(size_t)row * N + col] = l;
                } else if (MODE == 2) {
                    int b = row >> 11, st = row & 2047;
                    int hh = col >> 6, hd = col & 63;
                    size_t i0 = ((size_t)(b*H_ + hh)*64 + hd) * S_ + st;
                    __nv_bfloat16 h0 = __float2bfloat16(v0);
                    Chi[i0] = h0;
                    Clo[i0] = __float2bfloat16(v0 - __bfloat162float(h0));
                    __nv_bfloat16 h1 = __float2bfloat16(v1);
                    Chi[i0 + S_] = h1;
                    Clo[i0 + S_] = __float2bfloat16(v1 - __bfloat162float(h1));
                } else if (MODE == 3) {
                    uint32_t h, l;
                    split2u(gelu_f(v0), gelu_f(v1), h, l);
                    *(uint32_t*)&Chi[(size_t)row * N + col] = h;
                    *(uint32_t*)&Clo[(size_t)row * N + col] = l;
                } else { // MODE 4
                    if (tok >= 0) {
                        atomicAdd(&C[(size_t)tok * N + col],     wgt * v0);
                        atomicAdd(&C[(size_t)tok * N + col + 1], wgt * v1);
                    }
                }
            }
        }
    }
}

// ------------------------- tensor-core flash attention (bf16x3) -------------------------
// q planes pre-scaled by (1/8)*log2(e). k planes [tok][D]. vt planes [B][H][hd][S].
#define KSH_ 0
#define KSL_ (64*72)
#define VSH_ (2*64*72)
#define VSL_ (3*64*72)

__global__ void __launch_bounds__(128, 3) k_flash_bf(
    const __nv_bfloat16* __restrict__ qhi, const __nv_bfloat16* __restrict__ qlo,
    const __nv_bfloat16* __restrict__ khi, const __nv_bfloat16* __restrict__ klo,
    const __nv_bfloat16* __restrict__ vthi, const __nv_bfloat16* __restrict__ vtlo,
    __nv_bfloat16* __restrict__ ohi, __nv_bfloat16* __restrict__ olo)
{
    __shared__ __align__(16) __nv_bfloat16 sm[4*64*72];

    const int tid  = threadIdx.x;
    const int lane = tid & 31, wid = tid >> 5;
    const int g = lane >> 2, tq = lane & 3;
    const int q0 = blockIdx.x * 64, h = blockIdx.y, b = blockIdx.z;
    const size_t tokbase = (size_t)b * S_ + q0 + wid * 16;

    // Q fragments hi/lo, 4 k16 steps over HD=64
    uint32_t qh[4][4], ql[4][4];
    {
        const __nv_bfloat16* qbh = qhi + tokbase * D_ + h * 64;
        const __nv_bfloat16* qbl = qlo + tokbase * D_ + h * 64;
        #pragma unroll
        for (int j = 0; j < 4; j++) {
            int k0 = j * 16 + 2 * tq;
            qh[j][0] = *(const uint32_t*)(qbh + (size_t)(g    ) * D_ + k0);
            qh[j][1] = *(const uint32_t*)(qbh + (size_t)(g + 8) * D_ + k0);
            qh[j][2] = *(const uint32_t*)(qbh + (size_t)(g    ) * D_ + k0 + 8);
            qh[j][3] = *(const uint32_t*)(qbh + (size_t)(g + 8) * D_ + k0 + 8);
            ql[j][0] = *(const uint32_t*)(qbl + (size_t)(g    ) * D_ + k0);
            ql[j][1] = *(const uint32_t*)(qbl + (size_t)(g + 8) * D_ + k0);
            ql[j][2] = *(const uint32_t*)(qbl + (size_t)(g    ) * D_ + k0 + 8);
            ql[j][3] = *(const uint32_t*)(qbl + (size_t)(g + 8) * D_ + k0 + 8);
        }
    }
    const __nv_bfloat16* kbh = khi + ((size_t)b * S_) * D_ + h * 64;
    const __nv_bfloat16* kbl = klo + ((size_t)b * S_) * D_ + h * 64;
    const __nv_bfloat16* vbh = vthi + ((size_t)(b*H_ + h) * 64) * S_;
    const __nv_bfloat16* vbl = vtlo + ((size_t)(b*H_ + h) * 64) * S_;
    const uint32_t sbase = (uint32_t)__cvta_generic_to_shared(sm);
    const uint32_t b_lsel = (lane & 7) * 144 + ((lane >> 3) & 1) * 16;  // bytes

    float oc[8][4];
    #pragma unroll
    for (int n = 0; n < 8; n++)
        #pragma unroll
        for (int c = 0; c < 4; c++) oc[n][c] = 0.f;
    float mr[2] = {-1e30f, -1e30f}, lr[2] = {0.f, 0.f};

    for (int kt = 0; kt < S_; kt += 64) {
        // load K and Vt tiles (hi+lo), 16 x 16B chunks per thread
        #pragma unroll
        for (int it = 0; it < 8; it++) {
            int rem = tid + (it & 3) * 128;
            int row = rem >> 3, c8 = rem & 7;
            const __nv_bfloat16* src = (it < 4 ? kbh : kbl) + (size_t)(kt + row) * D_ + c8 * 8;
            cp16(sm + (it < 4 ? KSH_ : KSL_) + row * 72 + c8 * 8, src, true);
        }
        #pragma unroll
        for (int it = 0; it < 8; it++) {
            int rem = tid + (it & 3) * 128;
            int row = rem >> 3, c8 = rem & 7;
            const __nv_bfloat16* src = (it < 4 ? vbh : vbl) + (size_t)row * S_ + kt + c8 * 8;
            cp16(sm + (it < 4 ? VSH_ : VSL_) + row * 72 + c8 * 8, src, true);
        }
        asm volatile("cp.async.commit_group;\n");
        asm volatile("cp.async.wait_group 0;\n");
        __syncthreads();

        // S = Q K^T (log2 domain)
        float sacc[8][4];
        #pragma unroll
        for (int n = 0; n < 8; n++)
            #pragma unroll
            for (int c = 0; c < 4; c++) sacc[n][c] = 0.f;
        #pragma unroll
        for (int j = 0; j < 4; j++) {
            #pragma unroll
            for (int n = 0; n < 8; n++) {
                uint32_t rb = sbase + (uint32_t)(n * 8) * 144 + b_lsel + j * 32;
                uint32_t bh[2], bl[2];
                ldsm2(bh, rb);
                ldsm2(bl, rb + KSL_*2);
                mma_bf16(sacc[n], qh[j], bh[0], bh[1]);
                mma_bf16(sacc[n], ql[j], bh[0], bh[1]);
                mma_bf16(sacc[n], qh[j], bl[0], bl[1]);
            }
        }

        // online softmax (rows g / g+8)
        float rmax[2] = {-1e30f, -1e30f};
        #pragma unroll
        for (int n = 0; n < 8; n++) {
            rmax[0] = fmaxf(rmax[0], fmaxf(sacc[n][0], sacc[n][1]));
            rmax[1] = fmaxf(rmax[1], fmaxf(sacc[n][2], sacc[n][3]));
        }
        #pragma unroll
        for (int off = 1; off <= 2; off <<= 1) {
            rmax[0] = fmaxf(rmax[0], __shfl_xor_sync(0xffffffffu, rmax[0], off));
            rmax[1] = fmaxf(rmax[1], __shfl_xor_sync(0xffffffffu, rmax[1], off));
        }
        float mnew[2] = { fmaxf(mr[0], rmax[0]), fmaxf(mr[1], rmax[1]) };
        float alpha[2] = { exp2_fast(mr[0] - mnew[0]), exp2_fast(mr[1] - mnew[1]) };
        float lsum[2] = {0.f, 0.f};
        #pragma unroll
        for (int n = 0; n < 8; n++) {
            sacc[n][0] = exp2_fast(sacc[n][0] - mnew[0]);
            sacc[n][1] = exp2_fast(sacc[n][1] - mnew[0]);
            sacc[n][2] = exp2_fast(sacc[n][2] - mnew[1]);
            sacc[n][3] = exp2_fast(sacc[n][3] - mnew[1]);
            lsum[0] += sacc[n][0] + sacc[n][1];
            lsum[1] += sacc[n][2] + sacc[n][3];
        }
        #pragma unroll
        for (int off = 1; off <= 2; off <<= 1) {
            lsum[0] += __shfl_xor_sync(0xffffffffu, lsum[0], off);
            lsum[1] += __shfl_xor_sync(0xffffffffu, lsum[1], off);
        }
        lr[0] = lr[0] * alpha[0] + lsum[0];
        lr[1] = lr[1] * alpha[1] + lsum[1];
        mr[0] = mnew[0]; mr[1] = mnew[1];

        // P stays in registers: pack into bf16 A-fragments (hi + lo)
        uint32_t ph[4][4], pl[4][4];
        #pragma unroll
        for (int j = 0; j < 4; j++) {
            split2u(sacc[2*j  ][0], sacc[2*j  ][1], ph[j][0], pl[j][0]);
            split2u(sacc[2*j  ][2], sacc[2*j  ][3], ph[j][1], pl[j][1]);
            split2u(sacc[2*j+1][0], sacc[2*j+1][1], ph[j][2], pl[j][2]);
            split2u(sacc[2*j+1][2], sacc[2*j+1][3], ph[j][3], pl[j][3]);
        }
        #pragma unroll
        for (int n = 0; n < 8; n++) {
            oc[n][0] *= alpha[0]; oc[n][1] *= alpha[0];
            oc[n][2] *= alpha[1]; oc[n][3] *= alpha[1];
        }

        // O += P V
        #pragma unroll
        for (int j = 0; j < 4; j++) {
            #pragma unroll
            for (int n = 0; n < 8; n++) {
                uint32_t rb = sbase + VSH_*2 + (uint32_t)(n * 8) * 144 + b_lsel + j * 32;
                uint32_t bh[2], bl[2];
                ldsm2(bh, rb);
                ldsm2(bl, rb + KSL_*2);
                mma_bf16(oc[n], ph[j], bh[0], bh[1]);
                mma_bf16(oc[n], pl[j], bh[0], bh[1]);
                mma_bf16(oc[n], ph[j], bl[0], bl[1]);
            }
        }
        __syncthreads();
    }

    float inv0 = 1.f / lr[0], inv1 = 1.f / lr[1];
    __nv_bfloat16* obh = ohi + tokbase * D_ + h * 64;
    __nv_bfloat16* obl = olo + tokbase * D_ + h * 64;
    #pragma unroll
    for (int n = 0; n < 8; n++) {
        int col = n*8 + 2*tq;
        uint32_t hw, lw;
        split2u(oc[n][0] * inv0, oc[n][1] * inv0, hw, lw);
        *(uint32_t*)(obh + (size_t)(g    ) * D_ + col) = hw;
        *(uint32_t*)(obl + (size_t)(g    ) * D_ + col) = lw;
        split2u(oc[n][2] * inv1, oc[n][3] * inv1, hw, lw);
        *(uint32_t*)(obh + (size_t)(g + 8) * D_ + col) = hw;
        *(uint32_t*)(obl + (size_t)(g + 8) * D_ + col) = lw;
    }
}

// ------------------------- residual + layernorm (+ optional split planes) -------------------------
__global__ void __launch_bounds__(256) k_add_ln(
    const float* __restrict__ x, const float* __restrict__ r,
    const float* __restrict__ g, const float* __restrict__ be,
    float* __restrict__ out, __nv_bfloat16* __restrict__ ohi, __nv_bfloat16* __restrict__ olo,
    int has_r)
{
    __shared__ float red[8];
    __shared__ float s_mu, s_inv;
    const int t = blockIdx.x;
    const int tid = threadIdx.x;
    const int c0 = tid * 4;

    float4 v = *(const float4*)&x[(size_t)t * D_ + c0];
    if (has_r) {
        float4 rv = *(const float4*)&r[(size_t)t * D_ + c0];
        v.x += rv.x; v.y += rv.y; v.z += rv.z; v.w += rv.w;
    }
    float s = v.x + v.y + v.z + v.w;
    #pragma unroll
    for (int o = 16; o > 0; o >>= 1) s += __shfl_down_sync(0xffffffffu, s, o);
    if ((tid & 31) == 0) red[tid >> 5] = s;
    __syncthreads();
    if (tid < 8) {
        s = red[tid];
        #pragma unroll
        for (int o = 4; o > 0; o >>= 1) s += __shfl_down_sync(0xffu, s, o);
        if (tid == 0) s_mu = s * (1.f / D_);
    }
    __syncthreads();
    const float mu = s_mu;
    float sq = (v.x-mu)*(v.x-mu) + (v.y-mu)*(v.y-mu) + (v.z-mu)*(v.z-mu) + (v.w-mu)*(v.w-mu);
    #pragma unroll
    for (int o = 16; o > 0; o >>= 1) sq += __shfl_down_sync(0xffffffffu, sq, o);
    __syncthreads();
    if ((tid & 31) == 0) red[tid >> 5] = sq;
    __syncthreads();
    if (tid < 8) {
        sq = red[tid];
        #pragma unroll
        for (int o = 4; o > 0; o >>= 1) sq += __shfl_down_sync(0xffu, sq, o);
        if (tid == 0) s_inv = rsqrtf(sq * (1.f / D_) + 1e-5f);
    }
    __syncthreads();
    const float inv = s_inv;
    float4 gv = *(const float4*)&g[c0];
    float4 bv = *(const float4*)&be[c0];
    float o0 = (v.x - mu) * inv * gv.x + bv.x;
    float o1 = (v.y - mu) * inv * gv.y + bv.y;
    float o2 = (v.z - mu) * inv * gv.z + bv.z;
    float o3 = (v.w - mu) * inv * gv.w + bv.w;
    *(float4*)&out[(size_t)t * D_ + c0] = make_float4(o0, o1, o2, o3);
    if (ohi) {
        uint32_t h, l;
        split2u(o0, o1, h, l);
        *(uint32_t*)&ohi[(size_t)t * D_ + c0] = h;
        *(uint32_t*)&olo[(size_t)t * D_ + c0] = l;
        split2u(o2, o3, h, l);
        *(uint32_t*)&ohi[(size_t)t * D_ + c0 + 2] = h;
        *(uint32_t*)&olo[(size_t)t * D_ + c0 + 2] = l;
    }
}

// ------------------------- MoE routing -------------------------
__global__ void k_init_small() {
    int i = threadIdx.x;
    if (i < E_) { g_cnt[i] = 0; g_rsum[i] = 0.f; }
}
__global__ void k_init_slots() {
    int i = blockIdx.x * 256 + threadIdx.x;
    if (i < NSLOT_) g_slot_tok[i] = -1;
}
__global__ void k_copy_macc() {
    size_t i = (size_t)blockIdx.x * 256 + threadIdx.x;
    g_macc[i] = g_x1[i];
}

__global__ void __launch_bounds__(256) k_routing(
    const float* __restrict__ gateW, const float* __restrict__ gateb)
{
    const int gtid = blockIdx.x * blockDim.x + threadIdx.x;
    const int t = gtid >> 5;
    const int lane = gtid & 31;
    if (t >= T_) return;
    const float* xr = g_x1 + (size_t)t * D_;
    float acc[E_];
    #pragma unroll
    for (int e = 0; e < E_; e++) acc[e] = 0.f;
    for (int d = lane; d < D_; d += 32) {
        float xv = xr[d];
        const float* gw = gateW + (size_t)d * E_;
        #pragma unroll
        for (int e = 0; e < E_; e++) acc[e] += xv * gw[e];
    }
    #pragma unroll
    for (int e = 0; e < E_; e++) {
        #pragma unroll
        for (int o = 16; o > 0; o >>= 1)
            acc[e] += __shfl_down_sync(0xffffffffu, acc[e], o);
    }
    if (lane == 0) {
        float p[E_];
        float mx = -1e30f;
        #pragma unroll
        for (int e = 0; e < E_; e++) { acc[e] += gateb[e]; mx = fmaxf(mx, acc[e]); }
        float ssum = 0.f;
        #pragma unroll
        for (int e = 0; e < E_; e++) { p[e] = expf(acc[e] - mx); ssum += p[e]; }
        float invs = 1.f / ssum;
        #pragma unroll
        for (int e = 0; e < E_; e++) { p[e] *= invs; atomicAdd(&g_rsum[e], p[e]); }
        int i0 = 0;
        #pragma unroll
        for (int e = 1; e < E_; e++) if (p[e] > p[i0]) i0 = e;
        int i1 = -1;
        #pragma unroll
        for (int e = 0; e < E_; e++)
            if (e != i0 && (i1 < 0 || p[e] > p[i1])) i1 = e;
        float wsum = p[i0] + p[i1];
        int pos0 = atomicAdd(&g_cnt[i0], 1);
        int pos1 = atomicAdd(&g_cnt[i1], 1);
        g_texp[2*t]   = i0; g_tpos[2*t]   = pos0; g_tw[2*t]   = p[i0] / wsum;
        g_texp[2*t+1] = i1; g_tpos[2*t+1] = pos1; g_tw[2*t+1] = p[i1] / wsum;
    }
}

__global__ void k_scan() {
    if (threadIdx.x == 0 && blockIdx.x == 0) {
        int o = 0;
        for (int e = 0; e < E_; e++) {
            g_offs[e] = o;
            o += ((g_cnt[e] + 127) >> 7) << 7;
        }
        g_offs[E_] = o;
    }
}

__global__ void k_fill_slots() {
    int i = blockIdx.x * 256 + threadIdx.x;
    if (i >= T_ * TOPK_) return;
    int e = g_texp[i];
    int slot = g_offs[e] + g_tpos[i];
    g_slot_tok[slot] = i >> 1;
    g_slot_w[slot] = g_tw[i];
}

__global__ void k_aux(float* __restrict__ out) {
    if (threadIdx.x == 0 && blockIdx.x == 0) {
        float a = 0.f;
        for (int e = 0; e < E_; e++)
            a += ((float)g_cnt[e] / (float)(T_ * TOPK_)) * (g_rsum[e] / (float)T_);
        out[0] = (float)E_ * a;
    }
}

// ------------------------- launch -------------------------
extern "C" void kernel_launch(void* const* d_in, const int* in_sizes, int n_in,
                              void* d_out, int out_size)
{
    const float* x     = (const float*)d_in[0];
    const float* Wq    = (const float*)d_in[1];
    const float* bq    = (const float*)d_in[2];
    const float* Wk    = (const float*)d_in[3];
    const float* bk    = (const float*)d_in[4];
    const float* Wv    = (const float*)d_in[5];
    const float* bv    = (const float*)d_in[6];
    const float* Wo    = (const float*)d_in[7];
    const float* bo    = (const float*)d_in[8];
    const float* g1    = (const float*)d_in[9];
    const float* beta1 = (const float*)d_in[10];
    const float* gateW = (const float*)d_in[11];
    const float* gateb = (const float*)d_in[12];
    const float* eW1   = (const float*)d_in[13];
    const float* eb1   = (const float*)d_in[14];
    const float* eW2   = (const float*)d_in[15];
    const float* eb2   = (const float*)d_in[16];
    const float* g2    = (const float*)d_in[17];
    const float* beta2 = (const float*)d_in[18];
    float* out = (float*)d_out;

    __nv_bfloat16 *pxhi,*pxlo,*pqhi,*pqlo,*pkhi,*pklo,*pvthi,*pvtlo,*pathi,*patlo,*px1hi,*px1lo,*phhi,*phlo;
    __nv_bfloat16 *pWqh,*pWql,*pWkh,*pWkl,*pWvh,*pWvl,*pWoh,*pWol,*pW1h,*pW1l,*pW2h,*pW2l;
    float *pproj, *px1, *pmacc;
    cudaGetSymbolAddress((void**)&pxhi,  g_xhi);  cudaGetSymbolAddress((void**)&pxlo,  g_xlo);
    cudaGetSymbolAddress((void**)&pqhi,  g_qhi);  cudaGetSymbolAddress((void**)&pqlo,  g_qlo);
    cudaGetSymbolAddress((void**)&pkhi,  g_khi);  cudaGetSymbolAddress((void**)&pklo,  g_klo);
    cudaGetSymbolAddress((void**)&pvthi, g_vthi); cudaGetSymbolAddress((void**)&pvtlo, g_vtlo);
    cudaGetSymbolAddress((void**)&pathi, g_athi); cudaGetSymbolAddress((void**)&patlo, g_atlo);
    cudaGetSymbolAddress((void**)&px1hi, g_x1hi); cudaGetSymbolAddress((void**)&px1lo, g_x1lo);
    cudaGetSymbolAddress((void**)&phhi,  g_hhi);  cudaGetSymbolAddress((void**)&phlo,  g_hlo);
    cudaGetSymbolAddress((void**)&pWqh,  g_Wqh);  cudaGetSymbolAddress((void**)&pWql,  g_Wql);
    cudaGetSymbolAddress((void**)&pWkh,  g_Wkh);  cudaGetSymbolAddress((void**)&pWkl,  g_Wkl);
    cudaGetSymbolAddress((void**)&pWvh,  g_Wvh);  cudaGetSymbolAddress((void**)&pWvl,  g_Wvl);
    cudaGetSymbolAddress((void**)&pWoh,  g_Woh);  cudaGetSymbolAddress((void**)&pWol,  g_Wol);
    cudaGetSymbolAddress((void**)&pW1h,  g_W1h);  cudaGetSymbolAddress((void**)&pW1l,  g_W1l);
    cudaGetSymbolAddress((void**)&pW2h,  g_W2h);  cudaGetSymbolAddress((void**)&pW2l,  g_W2l);
    cudaGetSymbolAddress((void**)&pproj, g_proj);
    cudaGetSymbolAddress((void**)&px1,   g_x1);
    cudaGetSymbolAddress((void**)&pmacc, g_macc);

    const int GEMM_SMEM = 4 * ASTG_ * 2;   // 81920 B
    cudaFuncSetAttribute(k_gemm_bf<0>, cudaFuncAttributeMaxDynamicSharedMemorySize, GEMM_SMEM);
    cudaFuncSetAttribute(k_gemm_bf<1>, cudaFuncAttributeMaxDynamicSharedMemorySize, GEMM_SMEM);
    cudaFuncSetAttribute(k_gemm_bf<2>, cudaFuncAttributeMaxDynamicSharedMemorySize, GEMM_SMEM);
    cudaFuncSetAttribute(k_gemm_bf<3>, cudaFuncAttributeMaxDynamicSharedMemorySize, GEMM_SMEM);
    cudaFuncSetAttribute(k_gemm_bf<4>, cudaFuncAttributeMaxDynamicSharedMemorySize, GEMM_SMEM);

    // --- pre-pass: split x, transpose+split weights ---
    k_asplit<<<(T_*D_/2 + 255)/256, 256>>>((const float2*)x, pxhi, pxlo, T_*D_/2);
    k_wT<<<dim3(D_/32, D_/32), 256>>>(Wq, pWqh, pWql, D_, D_);
    k_wT<<<dim3(D_/32, D_/32), 256>>>(Wk, pWkh, pWkl, D_, D_);
    k_wT<<<dim3(D_/32, D_/32), 256>>>(Wv, pWvh, pWvl, D_, D_);
    k_wT<<<dim3(D_/32, D_/32), 256>>>(Wo, pWoh, pWol, D_, D_);
    k_wT<<<dim3(F_/32, D_/32, E_), 256>>>(eW1, pW1h, pW1l, D_, F_);
    k_wT<<<dim3(D_/32, F_/32, E_), 256>>>(eW2, pW2h, pW2l, F_, D_);

    // --- attention block ---
    const float QSCALE = 0.125f * 1.4426950408889634f;   // 1/sqrt(HD) * log2(e)
    dim3 gproj(D_/128, T_/128);
    k_gemm_bf<1><<<gproj, 256, GEMM_SMEM>>>(pxhi, pxlo, pWqh, pWql, bq, nullptr, pqhi, pqlo, T_, D_, D_, QSCALE);
    k_gemm_bf<1><<<gproj, 256, GEMM_SMEM>>>(pxhi, pxlo, pWkh, pWkl, bk, nullptr, pkhi, pklo, T_, D_, D_, 1.f);
    k_gemm_bf<2><<<gproj, 256, GEMM_SMEM>>>(pxhi, pxlo, pWvh, pWvl, bv, nullptr, pvthi, pvtlo, T_, D_, D_, 1.f);
    k_flash_bf<<<dim3(S_/64, H_, B_), 128>>>(pqhi, pqlo, pkhi, pklo, pvthi, pvtlo, pathi, patlo);
    k_gemm_bf<0><<<gproj, 256, GEMM_SMEM>>>(pathi, patlo, pWoh, pWol, bo, pproj, nullptr, nullptr, T_, D_, D_, 1.f);
    k_add_ln<<<T_, 256>>>(x, pproj, g1, beta1, px1, px1hi, px1lo, 1);

    // --- MoE routing ---
    k_init_small<<<1, 32>>>();
    k_init_slots<<<(NSLOT_ + 255)/256, 256>>>();
    k_routing<<<T_/8, 256>>>(gateW, gateb);
    k_scan<<<1, 1>>>();
    k_fill_slots<<<(T_*TOPK_ + 255)/256, 256>>>();
    k_copy_macc<<<(T_*D_)/256, 256>>>();

    // --- expert FFN (sparse top-2, 128-padded segments, bf16x3) ---
    k_gemm_bf<3><<<dim3(F_/128, NSLOT_/128), 256, GEMM_SMEM>>>(px1hi, px1lo, pW1h, pW1l, eb1, nullptr, phhi, phlo, NSLOT_, F_, D_, 1.f);
    k_gemm_bf<4><<<dim3(D_/128, NSLOT_/128), 256, GEMM_SMEM>>>(phhi, phlo, pW2h, pW2l, eb2, pmacc, nullptr, nullptr, NSLOT_, D_, F_, 1.f);

    // --- final layernorm + aux loss ---
    k_add_ln<<<T_, 256>>>(pmacc, pmacc, g2, beta2, out, nullptr, nullptr, 0);
    if (out_size > T_*D_) k_aux<<<1, 1>>>(out + (size_t)T_*D_);
}

// round 10
// speedup vs baseline: 6.3787x; 1.4338x over previous
#include <cuda_runtime.h>
#include <cuda_fp16.h>
#include <math.h>
#include <stdint.h>

#define B_ 4
#define S_ 2048
#define D_ 1024
#define H_ 16
#define HD_ 64
#define F_ 4096
#define E_ 8
#define TOPK_ 2
#define T_ (B_*S_)                    // 8192 tokens
#define NSLOT_ (T_*TOPK_ + E_*128)    // 17408 padded expert slots

// ------------------------- static device scratch -------------------------
// fp16 planes: activations hi+lo (A operands), weights/K/V hi only (B operands)
__device__ __align__(16) __half g_xhi [(size_t)T_*D_];
__device__ __align__(16) __half g_xlo [(size_t)T_*D_];
__device__ __align__(16) __half g_qhi [(size_t)T_*D_];
__device__ __align__(16) __half g_qlo [(size_t)T_*D_];
__device__ __align__(16) __half g_khi [(size_t)T_*D_];
__device__ __align__(16) __half g_vthi[(size_t)T_*D_];   // [B][H][hd][S]
__device__ __align__(16) __half g_athi[(size_t)T_*D_];
__device__ __align__(16) __half g_atlo[(size_t)T_*D_];
__device__ __align__(16) __half g_x1hi[(size_t)T_*D_];
__device__ __align__(16) __half g_x1lo[(size_t)T_*D_];
__device__ __align__(16) __half g_hhi [(size_t)NSLOT_*F_];
__device__ __align__(16) __half g_hlo [(size_t)NSLOT_*F_];
// weights: transposed [N,K] fp16 hi plane only
__device__ __align__(16) __half g_Wqh[D_*D_];
__device__ __align__(16) __half g_Wkh[D_*D_];
__device__ __align__(16) __half g_Wvh[D_*D_];
__device__ __align__(16) __half g_Woh[D_*D_];
__device__ __align__(16) __half g_W1h[(size_t)E_*D_*F_];
__device__ __align__(16) __half g_W2h[(size_t)E_*F_*D_];
// fp32 buffers
__device__ __align__(16) float g_proj[(size_t)T_*D_];
__device__ __align__(16) float g_x1  [(size_t)T_*D_];
__device__ __align__(16) float g_macc[(size_t)T_*D_];
// routing
__device__ int   g_slot_tok[NSLOT_];
__device__ float g_slot_w[NSLOT_];
__device__ int   g_texp[T_*TOPK_];
__device__ int   g_tpos[T_*TOPK_];
__device__ float g_tw[T_*TOPK_];
__device__ int   g_cnt[E_];
__device__ float g_rsum[E_];
__device__ int   g_offs[E_+1];

// ------------------------- helpers -------------------------
// pack two fp32 -> f16x2 (v0 in lower half)
__device__ __forceinline__ uint32_t pkh(float lo, float hi) {
    uint32_t r;
    asm("cvt.rn.f16x2.f32 %0, %1, %2;" : "=r"(r) : "f"(hi), "f"(lo));
    return r;
}
// split (v0,v1) into fp16 hi word + fp16 lo residual word
__device__ __forceinline__ void split2h(float v0, float v1, uint32_t& h, uint32_t& l) {
    h = pkh(v0, v1);
    __half2 hh = *reinterpret_cast<__half2*>(&h);
    float r0 = v0 - __low2float(hh);
    float r1 = v1 - __high2float(hh);
    l = pkh(r0, r1);
}
__device__ __forceinline__ void mma_f16(float* d, const uint32_t* a, uint32_t b0, uint32_t b1) {
    asm volatile(
        "mma.sync.aligned.m16n8k16.row.col.f32.f16.f16.f32 "
        "{%0,%1,%2,%3}, {%4,%5,%6,%7}, {%8,%9}, {%0,%1,%2,%3};\n"
        : "+f"(d[0]), "+f"(d[1]), "+f"(d[2]), "+f"(d[3])
        : "r"(a[0]), "r"(a[1]), "r"(a[2]), "r"(a[3]), "r"(b0), "r"(b1));
}
__device__ __forceinline__ void ldsm4(uint32_t* r, uint32_t saddr) {
    asm volatile("ldmatrix.sync.aligned.m8n8.x4.shared.b16 {%0,%1,%2,%3}, [%4];"
        : "=r"(r[0]), "=r"(r[1]), "=r"(r[2]), "=r"(r[3]) : "r"(saddr));
}
__device__ __forceinline__ void ldsm2(uint32_t* r, uint32_t saddr) {
    asm volatile("ldmatrix.sync.aligned.m8n8.x2.shared.b16 {%0,%1}, [%2];"
        : "=r"(r[0]), "=r"(r[1]) : "r"(saddr));
}
__device__ __forceinline__ void cp16(void* dst, const void* src, bool p) {
    unsigned sa = (unsigned)__cvta_generic_to_shared(dst);
    int n = p ? 16 : 0;
    asm volatile("cp.async.cg.shared.global [%0], [%1], 16, %2;\n" :: "r"(sa), "l"(src), "r"(n));
}
__device__ __forceinline__ float gelu_f(float z) {
    return 0.5f * z * (1.0f + erff(z * 0.70710678118654752f));
}
__device__ __forceinline__ float exp2_fast(float x) {
    x = fmaxf(x, -120.0f);
    int   n = __float2int_rn(x);
    float f = x - (float)n;
    float p = 1.33336498e-3f;
    p = fmaf(p, f, 9.61793571e-3f);
    p = fmaf(p, f, 5.55041087e-2f);
    p = fmaf(p, f, 2.40226507e-1f);
    p = fmaf(p, f, 6.93147181e-1f);
    p = fmaf(p, f, 1.0f);
    return __uint_as_float(__float_as_uint(p) + ((unsigned)n << 23));
}

// ------------------------- pre-pass: split activations -------------------------
__global__ void k_asplit(const float2* __restrict__ src,
                         __half* __restrict__ hi, __half* __restrict__ lo, int n2) {
    int i = blockIdx.x * 256 + threadIdx.x;
    if (i < n2) {
        float2 v = src[i];
        uint32_t h, l;
        split2h(v.x, v.y, h, l);
        ((uint32_t*)hi)[i] = h;
        ((uint32_t*)lo)[i] = l;
    }
}

// ------------------------- pre-pass: transpose weights -> fp16 hi plane -------------------------
// W [K,N] fp32 -> Wh [N,K] fp16.  grid (N/32, K/32, batch), 256 threads.
__global__ void __launch_bounds__(256) k_wT(
    const float* __restrict__ W, __half* __restrict__ Wh, int K, int N)
{
    __shared__ float t[32][33];
    W  += (size_t)blockIdx.z * K * N;
    Wh += (size_t)blockIdx.z * K * N;
    const int n0 = blockIdx.x * 32, k0 = blockIdx.y * 32;
    const int tid = threadIdx.x;
    #pragma unroll
    for (int i = 0; i < 4; i++) {
        int idx = tid + i * 256;
        int r = idx >> 5, c = idx & 31;
        t[r][c] = W[(size_t)(k0 + r) * N + n0 + c];
    }
    __syncthreads();
    #pragma unroll
    for (int i = 0; i < 2; i++) {
        int idx = tid + i * 256;
        int nr = idx >> 4, kp = idx & 15;
        *(uint32_t*)&Wh[(size_t)(n0 + nr) * K + k0 + 2*kp] = pkh(t[2*kp][nr], t[2*kp + 1][nr]);
    }
}

// ------------------------- tensor-core GEMM (fp16x2: A split, B hi) -------------------------
// C = A[M,Kd] @ W[Kd,N] + bias. A as fp16 hi/lo planes; B transposed [N,Kd] fp16.
// MODE 0: fp32 store.  1: split-store hi(+lo if given), scaled.  2: V-transposed hi store.
// MODE 3: FFN1 (A gathered by slot_tok, gelu + split planes).  4: FFN2 (weighted atomicAdd).
#define KT_ 32
#define APL_ (128*40)        // halfs per plane per stage
#define A_ST (2*APL_)        // A stage = hi+lo planes
#define GEMM_SMEM ((2*A_ST + 2*APL_)*2)   // 61440 B

template<int MODE>
__global__ void __launch_bounds__(256, 2) k_gemm_hf(
    const __half* __restrict__ Ahi, const __half* __restrict__ Alo,
    const __half* __restrict__ Bh,
    const float* __restrict__ bias,
    float* __restrict__ C, __half* __restrict__ Chi, __half* __restrict__ Clo,
    int M, int N, int Kd, float oscale)
{
    extern __shared__ __half sgb[];
    __half* As = sgb;               // 2 stages x A_ST
    __half* Bs = sgb + 2*A_ST;      // 2 stages x APL_

    const int tid   = threadIdx.x;
    const int tileN = blockIdx.x * 128;
    const int tileM = blockIdx.y * 128;

    if (MODE == 3 || MODE == 4) {
        if (tileM >= g_offs[E_]) return;
        int expert = 0;
        #pragma unroll
        for (int i = 1; i < E_; i++) if (tileM >= g_offs[i]) expert = i;
        Bh   += (size_t)expert * Kd * N;
        bias += (size_t)expert * N;
    }

    // A loader: 4 chunks/thread/stage (2 planes x 128 rows x 4 chunks = 1024)
    const __half* aptr[4];
    bool apred[4];
    int adst[4];
    #pragma unroll
    for (int it = 0; it < 4; it++) {
        int cid = tid + it * 256;
        int p = cid >> 9, rem = cid & 511;
        int row = rem >> 2, c16 = rem & 3;
        int grow = tileM + row;
        const __half* abase = p ? Alo : Ahi;
        if (MODE == 3) {
            int tok = g_slot_tok[grow];
            apred[it] = tok >= 0;
            aptr[it] = abase + (size_t)(tok < 0 ? 0 : tok) * Kd + c16 * 8;
        } else {
            apred[it] = true;
            aptr[it] = abase + (size_t)grow * Kd + c16 * 8;
        }
        adst[it] = p * APL_ + row * 40 + c16 * 8;
    }
    // B loader: 2 chunks/thread/stage (128 rows x 4 chunks = 512)
    const __half* bptr[2];
    int bdst[2];
    #pragma unroll
    for (int it = 0; it < 2; it++) {
        int cid = tid + it * 256;
        int row = cid >> 2, c16 = cid & 3;
        bptr[it] = Bh + (size_t)(tileN + row) * Kd + c16 * 8;
        bdst[it] = row * 40 + c16 * 8;
    }

    const int lane = tid & 31;
    const int g = lane >> 2, tq = lane & 3;
    const int wid = tid >> 5, wm = wid & 3, wn = wid >> 2;
    const int KTILES = Kd / KT_;
    const uint32_t sbase = (uint32_t)__cvta_generic_to_shared(sgb);
    const uint32_t a_lsel = (lane & 15) * 80 + (lane >> 4) * 16;
    const uint32_t b_lsel = (lane & 7) * 80 + ((lane >> 3) & 1) * 16;

    float acc[2][8][4];
    #pragma unroll
    for (int mi = 0; mi < 2; mi++)
        #pragma unroll
        for (int n = 0; n < 8; n++)
            #pragma unroll
            for (int c = 0; c < 4; c++) acc[mi][n][c] = 0.f;

    auto load_stage = [&](int kt, int s) {
        #pragma unroll
        for (int it = 0; it < 4; it++)
            cp16(As + s*A_ST + adst[it], aptr[it] + (size_t)kt * KT_, apred[it]);
        #pragma unroll
        for (int it = 0; it < 2; it++)
            cp16(Bs + s*APL_ + bdst[it], bptr[it] + (size_t)kt * KT_, true);
        asm volatile("cp.async.commit_group;\n");
    };

    load_stage(0, 0);
    for (int kt = 0; kt < KTILES; kt++) {
        if (kt + 1 < KTILES) {
            load_stage(kt + 1, (kt + 1) & 1);
            asm volatile("cp.async.wait_group 1;\n");
        } else {
            asm volatile("cp.async.wait_group 0;\n");
        }
        __syncthreads();
        const uint32_t as0 = sbase + ((kt & 1) * A_ST) * 2;
        const uint32_t bs0 = sbase + (2*A_ST + (kt & 1) * APL_) * 2;
        #pragma unroll
        for (int t = 0; t < 2; t++) {
            const uint32_t kb = t * 32;
            uint32_t ah[2][4], al[2][4];
            #pragma unroll
            for (int mi = 0; mi < 2; mi++) {
                uint32_t ra = as0 + (uint32_t)(wm*32 + mi*16) * 80 + a_lsel + kb;
                ldsm4(ah[mi], ra);
                ldsm4(al[mi], ra + APL_*2);
            }
            #pragma unroll
            for (int n = 0; n < 8; n++) {
                uint32_t rb = bs0 + (uint32_t)(wn*64 + n*8) * 80 + b_lsel + kb;
                uint32_t b[2];
                ldsm2(b, rb);
                #pragma unroll
                for (int mi = 0; mi < 2; mi++) {
                    mma_f16(acc[mi][n], ah[mi], b[0], b[1]);
                    mma_f16(acc[mi][n], al[mi], b[0], b[1]);
                }
            }
        }
        __syncthreads();
    }

    // epilogue
    #pragma unroll
    for (int mi = 0; mi < 2; mi++) {
        #pragma unroll
        for (int rr = 0; rr < 2; rr++) {
            int row = tileM + wm*32 + mi*16 + g + rr*8;
            int tok = 0; float wgt = 0.f;
            if (MODE == 4) { tok = g_slot_tok[row]; wgt = g_slot_w[row]; }
            if (MODE == 3) { if (g_slot_tok[row] < 0) continue; }
            #pragma unroll
            for (int n = 0; n < 8; n++) {
                int col = tileN + wn*64 + n*8 + 2*tq;
                float v0 = acc[mi][n][rr*2 + 0] + bias[col];
                float v1 = acc[mi][n][rr*2 + 1] + bias[col + 1];
                if (MODE == 0) {
                    *(float2*)&C[(size_t)row * N + col] = make_float2(v0, v1);
                } else if (MODE == 1) {
                    uint32_t h, l;
                    split2h(v0 * oscale, v1 * oscale, h, l);
                    *(uint32_t*)&Chi[(size_t)row * N + col] = h;
                    if (Clo) *(uint32_t*)&Clo[(size_t)row * N + col] = l;
                } else if (MODE == 2) {
                    int b = row >> 11, st = row & 2047;
                    int hh = col >> 6, hd = col & 63;
                    size_t i0 = ((size_t)(b*H_ + hh)*64 + hd) * S_ + st;
                    Chi[i0]      = __float2half_rn(v0);
                    Chi[i0 + S_] = __float2half_rn(v1);
                } else if (MODE == 3) {
                    uint32_t h, l;
                    split2h(gelu_f(v0), gelu_f(v1), h, l);
                    *(uint32_t*)&Chi[(size_t)row * N + col] = h;
                    *(uint32_t*)&Clo[(size_t)row * N + col] = l;
                } else { // MODE 4
                    if (tok >= 0) {
                        atomicAdd(&C[(size_t)tok * N + col],     wgt * v0);
                        atomicAdd(&C[(size_t)tok * N + col + 1], wgt * v1);
                    }
                }
            }
        }
    }
}

// ------------------------- tensor-core flash attention (fp16x2) -------------------------
// q planes pre-scaled by (1/8)*log2(e), hi+lo. k hi [tok][D]. vt hi [B][H][hd][S].
#define FV_ (64*72)

__global__ void __launch_bounds__(128, 3) k_flash_hf(
    const __half* __restrict__ qhi, const __half* __restrict__ qlo,
    const __half* __restrict__ khi, const __half* __restrict__ vthi,
    __half* __restrict__ ohi, __half* __restrict__ olo)
{
    __shared__ __align__(16) __half sm[2*64*72];

    const int tid  = threadIdx.x;
    const int lane = tid & 31, wid = tid >> 5;
    const int g = lane >> 2, tq = lane & 3;
    const int q0 = blockIdx.x * 64, h = blockIdx.y, b = blockIdx.z;
    const size_t tokbase = (size_t)b * S_ + q0 + wid * 16;

    // Q fragments hi/lo, 4 k16 steps over HD=64
    uint32_t qh[4][4], ql[4][4];
    {
        const __half* qbh = qhi + tokbase * D_ + h * 64;
        const __half* qbl = qlo + tokbase * D_ + h * 64;
        #pragma unroll
        for (int j = 0; j < 4; j++) {
            int k0 = j * 16 + 2 * tq;
            qh[j][0] = *(const uint32_t*)(qbh + (size_t)(g    ) * D_ + k0);
            qh[j][1] = *(const uint32_t*)(qbh + (size_t)(g + 8) * D_ + k0);
            qh[j][2] = *(const uint32_t*)(qbh + (size_t)(g    ) * D_ + k0 + 8);
            qh[j][3] = *(const uint32_t*)(qbh + (size_t)(g + 8) * D_ + k0 + 8);
            ql[j][0] = *(const uint32_t*)(qbl + (size_t)(g    ) * D_ + k0);
            ql[j][1] = *(const uint32_t*)(qbl + (size_t)(g + 8) * D_ + k0);
            ql[j][2] = *(const uint32_t*)(qbl + (size_t)(g    ) * D_ + k0 + 8);
            ql[j][3] = *(const uint32_t*)(qbl + (size_t)(g + 8) * D_ + k0 + 8);
        }
    }
    const __half* kbh = khi + ((size_t)b * S_) * D_ + h * 64;
    const __half* vbh = vthi + ((size_t)(b*H_ + h) * 64) * S_;
    const uint32_t sbase = (uint32_t)__cvta_generic_to_shared(sm);
    const uint32_t b_lsel = (lane & 7) * 144 + ((lane >> 3) & 1) * 16;

    float oc[8][4];
    #pragma unroll
    for (int n = 0; n < 8; n++)
        #pragma unroll
        for (int c = 0; c < 4; c++) oc[n][c] = 0.f;
    float mr[2] = {-1e30f, -1e30f}, lr[2] = {0.f, 0.f};

    for (int kt = 0; kt < S_; kt += 64) {
        #pragma unroll
        for (int it = 0; it < 4; it++) {
            int rem = tid + it * 128;
            int row = rem >> 3, c8 = rem & 7;
            cp16(sm + row * 72 + c8 * 8, kbh + (size_t)(kt + row) * D_ + c8 * 8, true);
        }
        #pragma unroll
        for (int it = 0; it < 4; it++) {
            int rem = tid + it * 128;
            int row = rem >> 3, c8 = rem & 7;
            cp16(sm + FV_ + row * 72 + c8 * 8, vbh + (size_t)row * S_ + kt + c8 * 8, true);
        }
        asm volatile("cp.async.commit_group;\n");
        asm volatile("cp.async.wait_group 0;\n");
        __syncthreads();

        // S = Q K^T (log2 domain via Q pre-scale), fp16x2
        float sacc[8][4];
        #pragma unroll
        for (int n = 0; n < 8; n++)
            #pragma unroll
            for (int c = 0; c < 4; c++) sacc[n][c] = 0.f;
        #pragma unroll
        for (int j = 0; j < 4; j++) {
            #pragma unroll
            for (int n = 0; n < 8; n++) {
                uint32_t rb = sbase + (uint32_t)(n * 8) * 144 + b_lsel + j * 32;
                uint32_t bb[2];
                ldsm2(bb, rb);
                mma_f16(sacc[n], qh[j], bb[0], bb[1]);
                mma_f16(sacc[n], ql[j], bb[0], bb[1]);
            }
        }

        // online softmax (rows g / g+8)
        float rmax[2] = {-1e30f, -1e30f};
        #pragma unroll
        for (int n = 0; n < 8; n++) {
            rmax[0] = fmaxf(rmax[0], fmaxf(sacc[n][0], sacc[n][1]));
            rmax[1] = fmaxf(rmax[1], fmaxf(sacc[n][2], sacc[n][3]));
        }
        #pragma unroll
        for (int off = 1; off <= 2; off <<= 1) {
            rmax[0] = fmaxf(rmax[0], __shfl_xor_sync(0xffffffffu, rmax[0], off));
            rmax[1] = fmaxf(rmax[1], __shfl_xor_sync(0xffffffffu, rmax[1], off));
        }
        float mnew[2] = { fmaxf(mr[0], rmax[0]), fmaxf(mr[1], rmax[1]) };
        float alpha[2] = { exp2_fast(mr[0] - mnew[0]), exp2_fast(mr[1] - mnew[1]) };
        float lsum[2] = {0.f, 0.f};
        #pragma unroll
        for (int n = 0; n < 8; n++) {
            sacc[n][0] = exp2_fast(sacc[n][0] - mnew[0]);
            sacc[n][1] = exp2_fast(sacc[n][1] - mnew[0]);
            sacc[n][2] = exp2_fast(sacc[n][2] - mnew[1]);
            sacc[n][3] = exp2_fast(sacc[n][3] - mnew[1]);
            lsum[0] += sacc[n][0] + sacc[n][1];
            lsum[1] += sacc[n][2] + sacc[n][3];
        }
        #pragma unroll
        for (int off = 1; off <= 2; off <<= 1) {
            lsum[0] += __shfl_xor_sync(0xffffffffu, lsum[0], off);
            lsum[1] += __shfl_xor_sync(0xffffffffu, lsum[1], off);
        }
        lr[0] = lr[0] * alpha[0] + lsum[0];
        lr[1] = lr[1] * alpha[1] + lsum[1];
        mr[0] = mnew[0]; mr[1] = mnew[1];

        // P in registers as fp16 hi/lo A-fragments
        uint32_t ph[4][4], pl[4][4];
        #pragma unroll
        for (int j = 0; j < 4; j++) {
            split2h(sacc[2*j  ][0], sacc[2*j  ][1], ph[j][0], pl[j][0]);
            split2h(sacc[2*j  ][2], sacc[2*j  ][3], ph[j][1], pl[j][1]);
            split2h(sacc[2*j+1][0], sacc[2*j+1][1], ph[j][2], pl[j][2]);
            split2h(sacc[2*j+1][2], sacc[2*j+1][3], ph[j][3], pl[j][3]);
        }
        #pragma unroll
        for (int n = 0; n < 8; n++) {
            oc[n][0] *= alpha[0]; oc[n][1] *= alpha[0];
            oc[n][2] *= alpha[1]; oc[n][3] *= alpha[1];
        }

        // O += P V
        #pragma unroll
        for (int j = 0; j < 4; j++) {
            #pragma unroll
            for (int n = 0; n < 8; n++) {
                uint32_t rb = sbase + FV_*2 + (uint32_t)(n * 8) * 144 + b_lsel + j * 32;
                uint32_t bb[2];
                ldsm2(bb, rb);
                mma_f16(oc[n], ph[j], bb[0], bb[1]);
                mma_f16(oc[n], pl[j], bb[0], bb[1]);
            }
        }
        __syncthreads();
    }

    float inv0 = 1.f / lr[0], inv1 = 1.f / lr[1];
    __half* obh = ohi + tokbase * D_ + h * 64;
    __half* obl = olo + tokbase * D_ + h * 64;
    #pragma unroll
    for (int n = 0; n < 8; n++) {
        int col = n*8 + 2*tq;
        uint32_t hw, lw;
        split2h(oc[n][0] * inv0, oc[n][1] * inv0, hw, lw);
        *(uint32_t*)(obh + (size_t)(g    ) * D_ + col) = hw;
        *(uint32_t*)(obl + (size_t)(g    ) * D_ + col) = lw;
        split2h(oc[n][2] * inv1, oc[n][3] * inv1, hw, lw);
        *(uint32_t*)(obh + (size_t)(g + 8) * D_ + col) = hw;
        *(uint32_t*)(obl + (size_t)(g + 8) * D_ + col) = lw;
    }
}

// ------------------------- residual + layernorm -------------------------
__global__ void __launch_bounds__(256) k_add_ln(
    const float* __restrict__ x, const float* __restrict__ r,
    const float* __restrict__ g, const float* __restrict__ be,
    float* __restrict__ out, float* __restrict__ out2,
    __half* __restrict__ ohi, __half* __restrict__ olo,
    int has_r)
{
    __shared__ float red[8];
    __shared__ float s_mu, s_inv;
    const int t = blockIdx.x;
    const int tid = threadIdx.x;
    const int c0 = tid * 4;

    float4 v = *(const float4*)&x[(size_t)t * D_ + c0];
    if (has_r) {
        float4 rv = *(const float4*)&r[(size_t)t * D_ + c0];
        v.x += rv.x; v.y += rv.y; v.z += rv.z; v.w += rv.w;
    }
    float s = v.x + v.y + v.z + v.w;
    #pragma unroll
    for (int o = 16; o > 0; o >>= 1) s += __shfl_down_sync(0xffffffffu, s, o);
    if ((tid & 31) == 0) red[tid >> 5] = s;
    __syncthreads();
    if (tid < 8) {
        s = red[tid];
        #pragma unroll
        for (int o = 4; o > 0; o >>= 1) s += __shfl_down_sync(0xffu, s, o);
        if (tid == 0) s_mu = s * (1.f / D_);
    }
    __syncthreads();
    const float mu = s_mu;
    float sq = (v.x-mu)*(v.x-mu) + (v.y-mu)*(v.y-mu) + (v.z-mu)*(v.z-mu) + (v.w-mu)*(v.w-mu);
    #pragma unroll
    for (int o = 16; o > 0; o >>= 1) sq += __shfl_down_sync(0xffffffffu, sq, o);
    __syncthreads();
    if ((tid & 31) == 0) red[tid >> 5] = sq;
    __syncthreads();
    if (tid < 8) {
        sq = red[tid];
        #pragma unroll
        for (int o = 4; o > 0; o >>= 1) sq += __shfl_down_sync(0xffu, sq, o);
        if (tid == 0) s_inv = rsqrtf(sq * (1.f / D_) + 1e-5f);
    }
    __syncthreads();
    const float inv = s_inv;
    float4 gv = *(const float4*)&g[c0];
    float4 bv = *(const float4*)&be[c0];
    float o0 = (v.x - mu) * inv * gv.x + bv.x;
    float o1 = (v.y - mu) * inv * gv.y + bv.y;
    float o2 = (v.z - mu) * inv * gv.z + bv.z;
    float o3 = (v.w - mu) * inv * gv.w + bv.w;
    *(float4*)&out[(size_t)t * D_ + c0] = make_float4(o0, o1, o2, o3);
    if (out2) *(float4*)&out2[(size_t)t * D_ + c0] = make_float4(o0, o1, o2, o3);
    if (ohi) {
        uint32_t h, l;
        split2h(o0, o1, h, l);
        *(uint32_t*)&ohi[(size_t)t * D_ + c0] = h;
        *(uint32_t*)&olo[(size_t)t * D_ + c0] = l;
        split2h(o2, o3, h, l);
        *(uint32_t*)&ohi[(size_t)t * D_ + c0 + 2] = h;
        *(uint32_t*)&olo[(size_t)t * D_ + c0 + 2] = l;
    }
}

// ------------------------- MoE routing -------------------------
__global__ void k_init_small() {
    int i = threadIdx.x;
    if (i < E_) { g_cnt[i] = 0; g_rsum[i] = 0.f; }
}
__global__ void k_init_slots() {
    int i = blockIdx.x * 256 + threadIdx.x;
    if (i < NSLOT_) g_slot_tok[i] = -1;
}

__global__ void __launch_bounds__(256) k_routing(
    const float* __restrict__ gateW, const float* __restrict__ gateb)
{
    const int gtid = blockIdx.x * blockDim.x + threadIdx.x;
    const int t = gtid >> 5;
    const int lane = gtid & 31;
    if (t >= T_) return;
    const float* xr = g_x1 + (size_t)t * D_;
    float acc[E_];
    #pragma unroll
    for (int e = 0; e < E_; e++) acc[e] = 0.f;
    for (int d = lane; d < D_; d += 32) {
        float xv = xr[d];
        const float* gw = gateW + (size_t)d * E_;
        #pragma unroll
        for (int e = 0; e < E_; e++) acc[e] += xv * gw[e];
    }
    #pragma unroll
    for (int e = 0; e < E_; e++) {
        #pragma unroll
        for (int o = 16; o > 0; o >>= 1)
            acc[e] += __shfl_down_sync(0xffffffffu, acc[e], o);
    }
    if (lane == 0) {
        float p[E_];
        float mx = -1e30f;
        #pragma unroll
        for (int e = 0; e < E_; e++) { acc[e] += gateb[e]; mx = fmaxf(mx, acc[e]); }
        float ssum = 0.f;
        #pragma unroll
        for (int e = 0; e < E_; e++) { p[e] = expf(acc[e] - mx); ssum += p[e]; }
        float invs = 1.f / ssum;
        #pragma unroll
        for (int e = 0; e < E_; e++) { p[e] *= invs; atomicAdd(&g_rsum[e], p[e]); }
        int i0 = 0;
        #pragma unroll
        for (int e = 1; e < E_; e++) if (p[e] > p[i0]) i0 = e;
        int i1 = -1;
        #pragma unroll
        for (int e = 0; e < E_; e++)
            if (e != i0 && (i1 < 0 || p[e] > p[i1])) i1 = e;
        float wsum = p[i0] + p[i1];
        int pos0 = atomicAdd(&g_cnt[i0], 1);
        int pos1 = atomicAdd(&g_cnt[i1], 1);
        g_texp[2*t]   = i0; g_tpos[2*t]   = pos0; g_tw[2*t]   = p[i0] / wsum;
        g_texp[2*t+1] = i1; g_tpos[2*t+1] = pos1; g_tw[2*t+1] = p[i1] / wsum;
    }
}

__global__ void k_scan() {
    if (threadIdx.x == 0 && blockIdx.x == 0) {
        int o = 0;
        for (int e = 0; e < E_; e++) {
            g_offs[e] = o;
            o += ((g_cnt[e] + 127) >> 7) << 7;
        }
        g_offs[E_] = o;
    }
}

__global__ void k_fill_slots() {
    int i = blockIdx.x * 256 + threadIdx.x;
    if (i >= T_ * TOPK_) return;
    int e = g_texp[i];
    int slot = g_offs[e] + g_tpos[i];
    g_slot_tok[slot] = i >> 1;
    g_slot_w[slot] = g_tw[i];
}

__global__ void k_aux(float* __restrict__ out) {
    if (threadIdx.x == 0 && blockIdx.x == 0) {
        float a = 0.f;
        for (int e = 0; e < E_; e++)
            a += ((float)g_cnt[e] / (float)(T_ * TOPK_)) * (g_rsum[e] / (float)T_);
        out[0] = (float)E_ * a;
    }
}

// ------------------------- launch -------------------------
extern "C" void kernel_launch(void* const* d_in, const int* in_sizes, int n_in,
                              void* d_out, int out_size)
{
    const float* x     = (const float*)d_in[0];
    const float* Wq    = (const float*)d_in[1];
    const float* bq    = (const float*)d_in[2];
    const float* Wk    = (const float*)d_in[3];
    const float* bk    = (const float*)d_in[4];
    const float* Wv    = (const float*)d_in[5];
    const float* bv    = (const float*)d_in[6];
    const float* Wo    = (const float*)d_in[7];
    const float* bo    = (const float*)d_in[8];
    const float* g1    = (const float*)d_in[9];
    const float* beta1 = (const float*)d_in[10];
    const float* gateW = (const float*)d_in[11];
    const float* gateb = (const float*)d_in[12];
    const float* eW1   = (const float*)d_in[13];
    const float* eb1   = (const float*)d_in[14];
    const float* eW2   = (const float*)d_in[15];
    const float* eb2   = (const float*)d_in[16];
    const float* g2    = (const float*)d_in[17];
    const float* beta2 = (const float*)d_in[18];
    float* out = (float*)d_out;

    __half *pxhi,*pxlo,*pqhi,*pqlo,*pkhi,*pvthi,*pathi,*patlo,*px1hi,*px1lo,*phhi,*phlo;
    __half *pWqh,*pWkh,*pWvh,*pWoh,*pW1h,*pW2h;
    float *pproj, *px1, *pmacc;
    cudaGetSymbolAddress((void**)&pxhi,  g_xhi);  cudaGetSymbolAddress((void**)&pxlo,  g_xlo);
    cudaGetSymbolAddress((void**)&pqhi,  g_qhi);  cudaGetSymbolAddress((void**)&pqlo,  g_qlo);
    cudaGetSymbolAddress((void**)&pkhi,  g_khi);
    cudaGetSymbolAddress((void**)&pvthi, g_vthi);
    cudaGetSymbolAddress((void**)&pathi, g_athi); cudaGetSymbolAddress((void**)&patlo, g_atlo);
    cudaGetSymbolAddress((void**)&px1hi, g_x1hi); cudaGetSymbolAddress((void**)&px1lo, g_x1lo);
    cudaGetSymbolAddress((void**)&phhi,  g_hhi);  cudaGetSymbolAddress((void**)&phlo,  g_hlo);
    cudaGetSymbolAddress((void**)&pWqh,  g_Wqh);
    cudaGetSymbolAddress((void**)&pWkh,  g_Wkh);
    cudaGetSymbolAddress((void**)&pWvh,  g_Wvh);
    cudaGetSymbolAddress((void**)&pWoh,  g_Woh);
    cudaGetSymbolAddress((void**)&pW1h,  g_W1h);
    cudaGetSymbolAddress((void**)&pW2h,  g_W2h);
    cudaGetSymbolAddress((void**)&pproj, g_proj);
    cudaGetSymbolAddress((void**)&px1,   g_x1);
    cudaGetSymbolAddress((void**)&pmacc, g_macc);

    cudaFuncSetAttribute(k_gemm_hf<0>, cudaFuncAttributeMaxDynamicSharedMemorySize, GEMM_SMEM);
    cudaFuncSetAttribute(k_gemm_hf<1>, cudaFuncAttributeMaxDynamicSharedMemorySize, GEMM_SMEM);
    cudaFuncSetAttribute(k_gemm_hf<2>, cudaFuncAttributeMaxDynamicSharedMemorySize, GEMM_SMEM);
    cudaFuncSetAttribute(k_gemm_hf<3>, cudaFuncAttributeMaxDynamicSharedMemorySize, GEMM_SMEM);
    cudaFuncSetAttribute(k_gemm_hf<4>, cudaFuncAttributeMaxDynamicSharedMemorySize, GEMM_SMEM);

    // --- pre-pass: split x, transpose weights to fp16 hi plane ---
    k_asplit<<<(T_*D_/2 + 255)/256, 256>>>((const float2*)x, pxhi, pxlo, T_*D_/2);
    k_wT<<<dim3(D_/32, D_/32), 256>>>(Wq, pWqh, D_, D_);
    k_wT<<<dim3(D_/32, D_/32), 256>>>(Wk, pWkh, D_, D_);
    k_wT<<<dim3(D_/32, D_/32), 256>>>(Wv, pWvh, D_, D_);
    k_wT<<<dim3(D_/32, D_/32), 256>>>(Wo, pWoh, D_, D_);
    k_wT<<<dim3(F_/32, D_/32, E_), 256>>>(eW1, pW1h, D_, F_);
    k_wT<<<dim3(D_/32, F_/32, E_), 256>>>(eW2, pW2h, F_, D_);

    // --- attention block ---
    const float QSCALE = 0.125f * 1.4426950408889634f;   // 1/sqrt(HD) * log2(e)
    dim3 gproj(D_/128, T_/128);
    k_gemm_hf<1><<<gproj, 256, GEMM_SMEM>>>(pxhi, pxlo, pWqh, bq, nullptr, pqhi, pqlo, T_, D_, D_, QSCALE);
    k_gemm_hf<1><<<gproj, 256, GEMM_SMEM>>>(pxhi, pxlo, pWkh, bk, nullptr, pkhi, nullptr, T_, D_, D_, 1.f);
    k_gemm_hf<2><<<gproj, 256, GEMM_SMEM>>>(pxhi, pxlo, pWvh, bv, nullptr, pvthi, nullptr, T_, D_, D_, 1.f);
    k_flash_hf<<<dim3(S_/64, H_, B_), 128>>>(pqhi, pqlo, pkhi, pvthi, pathi, patlo);
    k_gemm_hf<0><<<gproj, 256, GEMM_SMEM>>>(pathi, patlo, pWoh, bo, pproj, nullptr, nullptr, T_, D_, D_, 1.f);
    // x1 = LN(x + proj); also macc = x1 and fp16 planes
    k_add_ln<<<T_, 256>>>(x, pproj, g1, beta1, px1, pmacc, px1hi, px1lo, 1);

    // --- MoE routing ---
    k_init_small<<<1, 32>>>();
    k_init_slots<<<(NSLOT_ + 255)/256, 256>>>();
    k_routing<<<T_/8, 256>>>(gateW, gateb);
    k_scan<<<1, 1>>>();
    k_fill_slots<<<(T_*TOPK_ + 255)/256, 256>>>();

    // --- expert FFN (fp16x2, sparse top-2, 128-padded segments) ---
    k_gemm_hf<3><<<dim3(F_/128, NSLOT_/128), 256, GEMM_SMEM>>>(px1hi, px1lo, pW1h, eb1, nullptr, phhi, phlo, NSLOT_, F_, D_, 1.f);
    k_gemm_hf<4><<<dim3(D_/128, NSLOT_/128), 256, GEMM_SMEM>>>(phhi, phlo, pW2h, eb2, pmacc, nullptr, nullptr, NSLOT_, D_, F_, 1.f);

    // --- final layernorm + aux loss ---
    k_add_ln<<<T_, 256>>>(pmacc, pmacc, g2, beta2, out, nullptr, nullptr, nullptr, 0);
    if (out_size > T_*D_) k_aux<<<1, 1>>>(out + (size_t)T_*D_);
}

// round 12
// speedup vs baseline: 8.5239x; 1.3363x over previous
#include <cuda_runtime.h>
#include <cuda_fp16.h>
#include <math.h>
#include <stdint.h>

#define B_ 4
#define S_ 2048
#define D_ 1024
#define H_ 16
#define HD_ 64
#define F_ 4096
#define E_ 8
#define TOPK_ 2
#define T_ (B_*S_)                    // 8192 tokens
#define NSLOT_ (T_*TOPK_ + E_*128)    // 17408 padded expert slots

// ------------------------- static device scratch -------------------------
__device__ __align__(16) __half g_xhi [(size_t)T_*D_];
__device__ __align__(16) __half g_xlo [(size_t)T_*D_];
__device__ __align__(16) __half g_qhi [(size_t)T_*D_];
__device__ __align__(16) __half g_qlo [(size_t)T_*D_];
__device__ __align__(16) __half g_khi [(size_t)T_*D_];
__device__ __align__(16) __half g_vthi[(size_t)T_*D_];   // [B][H][hd][S]
__device__ __align__(16) __half g_athi[(size_t)T_*D_];
__device__ __align__(16) __half g_atlo[(size_t)T_*D_];
__device__ __align__(16) __half g_x1hi[(size_t)T_*D_];
__device__ __align__(16) __half g_hhi [(size_t)NSLOT_*F_];
// weights: native [K,N] layout, fp16
__device__ __align__(16) __half g_Wqh[D_*D_];
__device__ __align__(16) __half g_Wkh[D_*D_];
__device__ __align__(16) __half g_Wvh[D_*D_];
__device__ __align__(16) __half g_Woh[D_*D_];
__device__ __align__(16) __half g_W1h[(size_t)E_*D_*F_];
__device__ __align__(16) __half g_W2h[(size_t)E_*F_*D_];
// fp32 buffers
__device__ __align__(16) float g_proj[(size_t)T_*D_];
__device__ __align__(16) float g_x1  [(size_t)T_*D_];
__device__ __align__(16) float g_y   [(size_t)2*T_*D_];   // per-rank expert outputs
// routing
__device__ int   g_slot_tok[NSLOT_];
__device__ int   g_slot_rank[NSLOT_];
__device__ float g_slot_w[NSLOT_];
__device__ int   g_texp[T_*TOPK_];
__device__ int   g_tpos[T_*TOPK_];
__device__ float g_tw[T_*TOPK_];
__device__ int   g_cnt[E_];
__device__ float g_rsum[E_];
__device__ int   g_offs[E_+1];

// ------------------------- helpers -------------------------
__device__ __forceinline__ uint32_t pkh(float lo, float hi) {
    uint32_t r;
    asm("cvt.rn.f16x2.f32 %0, %1, %2;" : "=r"(r) : "f"(hi), "f"(lo));
    return r;
}
__device__ __forceinline__ void split2h(float v0, float v1, uint32_t& h, uint32_t& l) {
    h = pkh(v0, v1);
    __half2 hh = *reinterpret_cast<__half2*>(&h);
    float r0 = v0 - __low2float(hh);
    float r1 = v1 - __high2float(hh);
    l = pkh(r0, r1);
}
__device__ __forceinline__ void mma_f16(float* d, const uint32_t* a, uint32_t b0, uint32_t b1) {
    asm volatile(
        "mma.sync.aligned.m16n8k16.row.col.f32.f16.f16.f32 "
        "{%0,%1,%2,%3}, {%4,%5,%6,%7}, {%8,%9}, {%0,%1,%2,%3};\n"
        : "+f"(d[0]), "+f"(d[1]), "+f"(d[2]), "+f"(d[3])
        : "r"(a[0]), "r"(a[1]), "r"(a[2]), "r"(a[3]), "r"(b0), "r"(b1));
}
__device__ __forceinline__ void ldsm4(uint32_t* r, uint32_t saddr) {
    asm volatile("ldmatrix.sync.aligned.m8n8.x4.shared.b16 {%0,%1,%2,%3}, [%4];"
        : "=r"(r[0]), "=r"(r[1]), "=r"(r[2]), "=r"(r[3]) : "r"(saddr));
}
__device__ __forceinline__ void ldsm2(uint32_t* r, uint32_t saddr) {
    asm volatile("ldmatrix.sync.aligned.m8n8.x2.shared.b16 {%0,%1}, [%2];"
        : "=r"(r[0]), "=r"(r[1]) : "r"(saddr));
}
__device__ __forceinline__ void ldsm2t(uint32_t* r, uint32_t saddr) {
    asm volatile("ldmatrix.sync.aligned.m8n8.x2.trans.shared.b16 {%0,%1}, [%2];"
        : "=r"(r[0]), "=r"(r[1]) : "r"(saddr));
}
__device__ __forceinline__ void cp16(void* dst, const void* src, bool p) {
    unsigned sa = (unsigned)__cvta_generic_to_shared(dst);
    int n = p ? 16 : 0;
    asm volatile("cp.async.cg.shared.global [%0], [%1], 16, %2;\n" :: "r"(sa), "l"(src), "r"(n));
}
__device__ __forceinline__ float gelu_f(float z) {
    return 0.5f * z * (1.0f + erff(z * 0.70710678118654752f));
}
__device__ __forceinline__ float exp2_fast(float x) {
    x = fmaxf(x, -120.0f);
    int   n = __float2int_rn(x);
    float f = x - (float)n;
    float p = 1.33336498e-3f;
    p = fmaf(p, f, 9.61793571e-3f);
    p = fmaf(p, f, 5.55041087e-2f);
    p = fmaf(p, f, 2.40226507e-1f);
    p = fmaf(p, f, 6.93147181e-1f);
    p = fmaf(p, f, 1.0f);
    return __uint_as_float(__float_as_uint(p) + ((unsigned)n << 23));
}

// ------------------------- pre-pass: split activations -------------------------
__global__ void k_asplit(const float2* __restrict__ src,
                         __half* __restrict__ hi, __half* __restrict__ lo, int n2) {
    int i = blockIdx.x * 256 + threadIdx.x;
    if (i < n2) {
        float2 v = src[i];
        uint32_t h, l;
        split2h(v.x, v.y, h, l);
        ((uint32_t*)hi)[i] = h;
        ((uint32_t*)lo)[i] = l;
    }
}

// ------------------------- pre-pass: streaming fp32 -> fp16 convert (no transpose) -------------------------
__global__ void k_wcvt(const float4* __restrict__ src, uint2* __restrict__ dst, int n4) {
    int i = blockIdx.x * 256 + threadIdx.x;
    if (i < n4) {
        float4 v = src[i];
        dst[i] = make_uint2(pkh(v.x, v.y), pkh(v.z, v.w));
    }
}

// ------------------------- tensor-core GEMM (A split optional, B native [K,N] fp16) -------------------------
// C = A[M,Kd] @ W[Kd,N] + bias.
// MODE 0: fp32 store.  1: fp16 store hi (+lo residual if Clo), scaled.  2: V-transposed hi store.
// MODE 3: FFN1 (A gathered by slot_tok, gelu -> hi).  4: FFN2 (weighted store to per-rank y).
#define KT_ 32
#define APL_ (128*40)        // halfs per A plane per stage
#define BPL_ (32*136)        // halfs per B stage (32 k-rows x 136)

template<int MODE, int ASPLIT>
__global__ void __launch_bounds__(256, 2) k_gemm_hf(
    const __half* __restrict__ Ahi, const __half* __restrict__ Alo,
    const __half* __restrict__ Bh,
    const float* __restrict__ bias,
    float* __restrict__ C, __half* __restrict__ Chi, __half* __restrict__ Clo,
    int M, int N, int Kd, float oscale)
{
    constexpr int A_ST = (ASPLIT ? 2 : 1) * APL_;   // halfs per A stage
    extern __shared__ __half sgb[];
    __half* As = sgb;               // 2 stages x A_ST
    __half* Bs = sgb + 2*A_ST;      // 2 stages x BPL_

    const int tid   = threadIdx.x;
    const int tileN = blockIdx.x * 128;
    const int tileM = blockIdx.y * 128;

    if (MODE == 3 || MODE == 4) {
        if (tileM >= g_offs[E_]) return;
        int expert = 0;
        #pragma unroll
        for (int i = 1; i < E_; i++) if (tileM >= g_offs[i]) expert = i;
        Bh   += (size_t)expert * Kd * N;
        bias += (size_t)expert * N;
    }

    // A loader: (ASPLIT?4:2) chunks/thread/stage
    constexpr int ACH = ASPLIT ? 4 : 2;
    const __half* aptr[ACH];
    bool apred[ACH];
    int adst[ACH];
    #pragma unroll
    for (int it = 0; it < ACH; it++) {
        int cid = tid + it * 256;
        int p = ASPLIT ? (cid >> 9) : 0;
        int rem = ASPLIT ? (cid & 511) : cid;
        int row = rem >> 2, c16 = rem & 3;
        int grow = tileM + row;
        const __half* abase = p ? Alo : Ahi;
        if (MODE == 3) {
            int tok = g_slot_tok[grow];
            apred[it] = tok >= 0;
            aptr[it] = abase + (size_t)(tok < 0 ? 0 : tok) * Kd + c16 * 8;
        } else {
            apred[it] = true;
            aptr[it] = abase + (size_t)grow * Kd + c16 * 8;
        }
        adst[it] = p * APL_ + row * 40 + c16 * 8;
    }
    // B loader: 2 chunks/thread/stage; B tile = 32 k-rows x 128 n-cols from [K,N]
    const __half* bptr[2];
    int bdst[2];
    #pragma unroll
    for (int it = 0; it < 2; it++) {
        int cid = tid + it * 256;
        int row = cid >> 4, c16 = cid & 15;
        bptr[it] = Bh + (size_t)row * N + tileN + c16 * 8;
        bdst[it] = row * 136 + c16 * 8;
    }

    const int lane = tid & 31;
    const int g = lane >> 2, tq = lane & 3;
    const int wid = tid >> 5, wm = wid & 3, wn = wid >> 2;
    const int KTILES = Kd / KT_;
    const uint32_t sbase = (uint32_t)__cvta_generic_to_shared(sgb);
    const uint32_t a_lsel = (lane & 15) * 80 + (lane >> 4) * 16;   // bytes
    const uint32_t b_lsel = (lane & 15) * 272;                     // bytes (row stride 136 halfs)

    float acc[2][8][4];
    #pragma unroll
    for (int mi = 0; mi < 2; mi++)
        #pragma unroll
        for (int n = 0; n < 8; n++)
            #pragma unroll
            for (int c = 0; c < 4; c++) acc[mi][n][c] = 0.f;

    auto load_stage = [&](int kt, int s) {
        #pragma unroll
        for (int it = 0; it < ACH; it++)
            cp16(As + s*A_ST + adst[it], aptr[it] + (size_t)kt * KT_, apred[it]);
        #pragma unroll
        for (int it = 0; it < 2; it++)
            cp16(Bs + s*BPL_ + bdst[it], bptr[it] + (size_t)kt * KT_ * N, true);
        asm volatile("cp.async.commit_group;\n");
    };

    load_stage(0, 0);
    for (int kt = 0; kt < KTILES; kt++) {
        if (kt + 1 < KTILES) {
            load_stage(kt + 1, (kt + 1) & 1);
            asm volatile("cp.async.wait_group 1;\n");
        } else {
            asm volatile("cp.async.wait_group 0;\n");
        }
        __syncthreads();
        const uint32_t as0 = sbase + ((kt & 1) * A_ST) * 2;
        const uint32_t bs0 = sbase + (2*A_ST + (kt & 1) * BPL_) * 2;
        #pragma unroll
        for (int t = 0; t < 2; t++) {
            uint32_t ah[2][4], al[2][4];
            #pragma unroll
            for (int mi = 0; mi < 2; mi++) {
                uint32_t ra = as0 + (uint32_t)(wm*32 + mi*16) * 80 + a_lsel + t * 32;
                ldsm4(ah[mi], ra);
                if (ASPLIT) ldsm4(al[mi], ra + APL_*2);
            }
            #pragma unroll
            for (int n = 0; n < 8; n++) {
                // B fragment via trans-ldmatrix from [k,n] tile: rows t*16+(lane&15), col wn*64+n*8
                uint32_t rb = bs0 + (uint32_t)t * 4352 + b_lsel + (uint32_t)(wn*64 + n*8) * 2;
                uint32_t b[2];
                ldsm2t(b, rb);
                #pragma unroll
                for (int mi = 0; mi < 2; mi++) {
                    mma_f16(acc[mi][n], ah[mi], b[0], b[1]);
                    if (ASPLIT) mma_f16(acc[mi][n], al[mi], b[0], b[1]);
                }
            }
        }
        __syncthreads();
    }

    // epilogue
    #pragma unroll
    for (int mi = 0; mi < 2; mi++) {
        #pragma unroll
        for (int rr = 0; rr < 2; rr++) {
            int row = tileM + wm*32 + mi*16 + g + rr*8;
            int tok = 0, rank = 0; float wgt = 0.f;
            if (MODE == 4) {
                tok = g_slot_tok[row];
                if (tok >= 0) { rank = g_slot_rank[row]; wgt = g_slot_w[row]; }
            }
            if (MODE == 3) { if (g_slot_tok[row] < 0) continue; }
            #pragma unroll
            for (int n = 0; n < 8; n++) {
                int col = tileN + wn*64 + n*8 + 2*tq;
                float v0 = acc[mi][n][rr*2 + 0] + bias[col];
                float v1 = acc[mi][n][rr*2 + 1] + bias[col + 1];
                if (MODE == 0) {
                    *(float2*)&C[(size_t)row * N + col] = make_float2(v0, v1);
                } else if (MODE == 1) {
                    if (Clo) {
                        uint32_t h, l;
                        split2h(v0 * oscale, v1 * oscale, h, l);
                        *(uint32_t*)&Chi[(size_t)row * N + col] = h;
                        *(uint32_t*)&Clo[(size_t)row * N + col] = l;
                    } else {
                        *(uint32_t*)&Chi[(size_t)row * N + col] = pkh(v0 * oscale, v1 * oscale);
                    }
                } else if (MODE == 2) {
                    int b = row >> 11, st = row & 2047;
                    int hh = col >> 6, hd = col & 63;
                    size_t i0 = ((size_t)(b*H_ + hh)*64 + hd) * S_ + st;
                    Chi[i0]      = __float2half_rn(v0);
                    Chi[i0 + S_] = __float2half_rn(v1);
                } else if (MODE == 3) {
                    *(uint32_t*)&Chi[(size_t)row * N + col] = pkh(gelu_f(v0), gelu_f(v1));
                } else { // MODE 4: weighted store to per-rank y buffer
                    if (tok >= 0) {
                        *(float2*)&C[((size_t)rank * T_ + tok) * N + col] =
                            make_float2(wgt * v0, wgt * v1);
                    }
                }
            }
        }
    }
}

// ------------------------- tensor-core flash attention (fp16x2) -------------------------
#define FV_ (64*72)

__global__ void __launch_bounds__(128, 3) k_flash_hf(
    const __half* __restrict__ qhi, const __half* __restrict__ qlo,
    const __half* __restrict__ khi, const __half* __restrict__ vthi,
    __half* __restrict__ ohi, __half* __restrict__ olo)
{
    __shared__ __align__(16) __half sm[2*64*72];

    const int tid  = threadIdx.x;
    const int lane = tid & 31, wid = tid >> 5;
    const int g = lane >> 2, tq = lane & 3;
    const int q0 = blockIdx.x * 64, h = blockIdx.y, b = blockIdx.z;
    const size_t tokbase = (size_t)b * S_ + q0 + wid * 16;

    uint32_t qh[4][4], ql[4][4];
    {
        const __half* qbh = qhi + tokbase * D_ + h * 64;
        const __half* qbl = qlo + tokbase * D_ + h * 64;
        #pragma unroll
        for (int j = 0; j < 4; j++) {
            int k0 = j * 16 + 2 * tq;
            qh[j][0] = *(const uint32_t*)(qbh + (size_t)(g    ) * D_ + k0);
            qh[j][1] = *(const uint32_t*)(qbh + (size_t)(g + 8) * D_ + k0);
            qh[j][2] = *(const uint32_t*)(qbh + (size_t)(g    ) * D_ + k0 + 8);
            qh[j][3] = *(const uint32_t*)(qbh + (size_t)(g + 8) * D_ + k0 + 8);
            ql[j][0] = *(const uint32_t*)(qbl + (size_t)(g    ) * D_ + k0);
            ql[j][1] = *(const uint32_t*)(qbl + (size_t)(g + 8) * D_ + k0);
            ql[j][2] = *(const uint32_t*)(qbl + (size_t)(g    ) * D_ + k0 + 8);
            ql[j][3] = *(const uint32_t*)(qbl + (size_t)(g + 8) * D_ + k0 + 8);
        }
    }
    const __half* kbh = khi + ((size_t)b * S_) * D_ + h * 64;
    const __half* vbh = vthi + ((size_t)(b*H_ + h) * 64) * S_;
    const uint32_t sbase = (uint32_t)__cvta_generic_to_shared(sm);
    const uint32_t b_lsel = (lane & 7) * 144 + ((lane >> 3) & 1) * 16;

    float oc[8][4];
    #pragma unroll
    for (int n = 0; n < 8; n++)
        #pragma unroll
        for (int c = 0; c < 4; c++) oc[n][c] = 0.f;
    float mr[2] = {-1e30f, -1e30f}, lr[2] = {0.f, 0.f};

    for (int kt = 0; kt < S_; kt += 64) {
        #pragma unroll
        for (int it = 0; it < 4; it++) {
            int rem = tid + it * 128;
            int row = rem >> 3, c8 = rem & 7;
            cp16(sm + row * 72 + c8 * 8, kbh + (size_t)(kt + row) * D_ + c8 * 8, true);
        }
        #pragma unroll
        for (int it = 0; it < 4; it++) {
            int rem = tid + it * 128;
            int row = rem >> 3, c8 = rem & 7;
            cp16(sm + FV_ + row * 72 + c8 * 8, vbh + (size_t)row * S_ + kt + c8 * 8, true);
        }
        asm volatile("cp.async.commit_group;\n");
        asm volatile("cp.async.wait_group 0;\n");
        __syncthreads();

        float sacc[8][4];
        #pragma unroll
        for (int n = 0; n < 8; n++)
            #pragma unroll
            for (int c = 0; c < 4; c++) sacc[n][c] = 0.f;
        #pragma unroll
        for (int j = 0; j < 4; j++) {
            #pragma unroll
            for (int n = 0; n < 8; n++) {
                uint32_t rb = sbase + (uint32_t)(n * 8) * 144 + b_lsel + j * 32;
                uint32_t bb[2];
                ldsm2(bb, rb);
                mma_f16(sacc[n], qh[j], bb[0], bb[1]);
                mma_f16(sacc[n], ql[j], bb[0], bb[1]);
            }
        }

        float rmax[2] = {-1e30f, -1e30f};
        #pragma unroll
        for (int n = 0; n < 8; n++) {
            rmax[0] = fmaxf(rmax[0], fmaxf(sacc[n][0], sacc[n][1]));
            rmax[1] = fmaxf(rmax[1], fmaxf(sacc[n][2], sacc[n][3]));
        }
        #pragma unroll
        for (int off = 1; off <= 2; off <<= 1) {
            rmax[0] = fmaxf(rmax[0], __shfl_xor_sync(0xffffffffu, rmax[0], off));
            rmax[1] = fmaxf(rmax[1], __shfl_xor_sync(0xffffffffu, rmax[1], off));
        }
        float mnew[2] = { fmaxf(mr[0], rmax[0]), fmaxf(mr[1], rmax[1]) };
        float alpha[2] = { exp2_fast(mr[0] - mnew[0]), exp2_fast(mr[1] - mnew[1]) };
        float lsum[2] = {0.f, 0.f};
        #pragma unroll
        for (int n = 0; n < 8; n++) {
            sacc[n][0] = exp2_fast(sacc[n][0] - mnew[0]);
            sacc[n][1] = exp2_fast(sacc[n][1] - mnew[0]);
            sacc[n][2] = exp2_fast(sacc[n][2] - mnew[1]);
            sacc[n][3] = exp2_fast(sacc[n][3] - mnew[1]);
            lsum[0] += sacc[n][0] + sacc[n][1];
            lsum[1] += sacc[n][2] + sacc[n][3];
        }
        #pragma unroll
        for (int off = 1; off <= 2; off <<= 1) {
            lsum[0] += __shfl_xor_sync(0xffffffffu, lsum[0], off);
            lsum[1] += __shfl_xor_sync(0xffffffffu, lsum[1], off);
        }
        lr[0] = lr[0] * alpha[0] + lsum[0];
        lr[1] = lr[1] * alpha[1] + lsum[1];
        mr[0] = mnew[0]; mr[1] = mnew[1];

        uint32_t ph[4][4], pl[4][4];
        #pragma unroll
        for (int j = 0; j < 4; j++) {
            split2h(sacc[2*j  ][0], sacc[2*j  ][1], ph[j][0], pl[j][0]);
            split2h(sacc[2*j  ][2], sacc[2*j  ][3], ph[j][1], pl[j][1]);
            split2h(sacc[2*j+1][0], sacc[2*j+1][1], ph[j][2], pl[j][2]);
            split2h(sacc[2*j+1][2], sacc[2*j+1][3], ph[j][3], pl[j][3]);
        }
        #pragma unroll
        for (int n = 0; n < 8; n++) {
            oc[n][0] *= alpha[0]; oc[n][1] *= alpha[0];
            oc[n][2] *= alpha[1]; oc[n][3] *= alpha[1];
        }

        #pragma unroll
        for (int j = 0; j < 4; j++) {
            #pragma unroll
            for (int n = 0; n < 8; n++) {
                uint32_t rb = sbase + FV_*2 + (uint32_t)(n * 8) * 144 + b_lsel + j * 32;
                uint32_t bb[2];
                ldsm2(bb, rb);
                mma_f16(oc[n], ph[j], bb[0], bb[1]);
                mma_f16(oc[n], pl[j], bb[0], bb[1]);
            }
        }
        __syncthreads();
    }

    float inv0 = 1.f / lr[0], inv1 = 1.f / lr[1];
    __half* obh = ohi + tokbase * D_ + h * 64;
    __half* obl = olo + tokbase * D_ + h * 64;
    #pragma unroll
    for (int n = 0; n < 8; n++) {
        int col = n*8 + 2*tq;
        uint32_t hw, lw;
        split2h(oc[n][0] * inv0, oc[n][1] * inv0, hw, lw);
        *(uint32_t*)(obh + (size_t)(g    ) * D_ + col) = hw;
        *(uint32_t*)(obl + (size_t)(g    ) * D_ + col) = lw;
        split2h(oc[n][2] * inv1, oc[n][3] * inv1, hw, lw);
        *(uint32_t*)(obh + (size_t)(g + 8) * D_ + col) = hw;
        *(uint32_t*)(obl + (size_t)(g + 8) * D_ + col) = lw;
    }
}

// ------------------------- residual + layernorm (x + r), writes fp32 + fp16 hi -------------------------
__global__ void __launch_bounds__(256) k_add_ln(
    const float* __restrict__ x, const float* __restrict__ r,
    const float* __restrict__ g, const float* __restrict__ be,
    float* __restrict__ out, __half* __restrict__ ohi)
{
    __shared__ float red[8];
    __shared__ float s_mu, s_inv;
    const int t = blockIdx.x;
    const int tid = threadIdx.x;
    const int c0 = tid * 4;

    float4 v = *(const float4*)&x[(size_t)t * D_ + c0];
    float4 rv = *(const float4*)&r[(size_t)t * D_ + c0];
    v.x += rv.x; v.y += rv.y; v.z += rv.z; v.w += rv.w;
    float s = v.x + v.y + v.z + v.w;
    #pragma unroll
    for (int o = 16; o > 0; o >>= 1) s += __shfl_down_sync(0xffffffffu, s, o);
    if ((tid & 31) == 0) red[tid >> 5] = s;
    __syncthreads();
    if (tid < 8) {
        s = red[tid];
        #pragma unroll
        for (int o = 4; o > 0; o >>= 1) s += __shfl_down_sync(0xffu, s, o);
        if (tid == 0) s_mu = s * (1.f / D_);
    }
    __syncthreads();
    const float mu = s_mu;
    float sq = (v.x-mu)*(v.x-mu) + (v.y-mu)*(v.y-mu) + (v.z-mu)*(v.z-mu) + (v.w-mu)*(v.w-mu);
    #pragma unroll
    for (int o = 16; o > 0; o >>= 1) sq += __shfl_down_sync(0xffffffffu, sq, o);
    __syncthreads();
    if ((tid & 31) == 0) red[tid >> 5] = sq;
    __syncthreads();
    if (tid < 8) {
        sq = red[tid];
        #pragma unroll
        for (int o = 4; o > 0; o >>= 1) sq += __shfl_down_sync(0xffu, sq, o);
        if (tid == 0) s_inv = rsqrtf(sq * (1.f / D_) + 1e-5f);
    }
    __syncthreads();
    const float inv = s_inv;
    float4 gv = *(const float4*)&g[c0];
    float4 bv = *(const float4*)&be[c0];
    float o0 = (v.x - mu) * inv * gv.x + bv.x;
    float o1 = (v.y - mu) * inv * gv.y + bv.y;
    float o2 = (v.z - mu) * inv * gv.z + bv.z;
    float o3 = (v.w - mu) * inv * gv.w + bv.w;
    *(float4*)&out[(size_t)t * D_ + c0] = make_float4(o0, o1, o2, o3);
    *(uint32_t*)&ohi[(size_t)t * D_ + c0]     = pkh(o0, o1);
    *(uint32_t*)&ohi[(size_t)t * D_ + c0 + 2] = pkh(o2, o3);
}

// ------------------------- final layernorm: LN(x1 + y0 + y1) -------------------------
__global__ void __launch_bounds__(256) k_ln3(
    const float* __restrict__ x1, const float* __restrict__ y,
    const float* __restrict__ g, const float* __restrict__ be,
    float* __restrict__ out)
{
    __shared__ float red[8];
    __shared__ float s_mu, s_inv;
    const int t = blockIdx.x;
    const int tid = threadIdx.x;
    const int c0 = tid * 4;

    float4 v  = *(const float4*)&x1[(size_t)t * D_ + c0];
    float4 y0 = *(const float4*)&y[(size_t)t * D_ + c0];
    float4 y1 = *(const float4*)&y[(size_t)(T_ + t) * D_ + c0];
    v.x += y0.x + y1.x; v.y += y0.y + y1.y; v.z += y0.z + y1.z; v.w += y0.w + y1.w;
    float s = v.x + v.y + v.z + v.w;
    #pragma unroll
    for (int o = 16; o > 0; o >>= 1) s += __shfl_down_sync(0xffffffffu, s, o);
    if ((tid & 31) == 0) red[tid >> 5] = s;
    __syncthreads();
    if (tid < 8) {
        s = red[tid];
        #pragma unroll
        for (int o = 4; o > 0; o >>= 1) s += __shfl_down_sync(0xffu, s, o);
        if (tid == 0) s_mu = s * (1.f / D_);
    }
    __syncthreads();
    const float mu = s_mu;
    float sq = (v.x-mu)*(v.x-mu) + (v.y-mu)*(v.y-mu) + (v.z-mu)*(v.z-mu) + (v.w-mu)*(v.w-mu);
    #pragma unroll
    for (int o = 16; o > 0; o >>= 1) sq += __shfl_down_sync(0xffffffffu, sq, o);
    __syncthreads();
    if ((tid & 31) == 0) red[tid >> 5] = sq;
    __syncthreads();
    if (tid < 8) {
        sq = red[tid];
        #pragma unroll
        for (int o = 4; o > 0; o >>= 1) sq += __shfl_down_sync(0xffu, sq, o);
        if (tid == 0) s_inv = rsqrtf(sq * (1.f / D_) + 1e-5f);
    }
    __syncthreads();
    const float inv = s_inv;
    float4 gv = *(const float4*)&g[c0];
    float4 bv = *(const float4*)&be[c0];
    *(float4*)&out[(size_t)t * D_ + c0] = make_float4(
        (v.x - mu) * inv * gv.x + bv.x,
        (v.y - mu) * inv * gv.y + bv.y,
        (v.z - mu) * inv * gv.z + bv.z,
        (v.w - mu) * inv * gv.w + bv.w);
}

// ------------------------- MoE routing -------------------------
__global__ void k_init_small() {
    int i = threadIdx.x;
    if (i < E_) { g_cnt[i] = 0; g_rsum[i] = 0.f; }
}
__global__ void k_init_slots() {
    int i = blockIdx.x * 256 + threadIdx.x;
    if (i < NSLOT_) g_slot_tok[i] = -1;
}

__global__ void __launch_bounds__(256) k_routing(
    const float* __restrict__ gateW, const float* __restrict__ gateb)
{
    const int gtid = blockIdx.x * blockDim.x + threadIdx.x;
    const int t = gtid >> 5;
    const int lane = gtid & 31;
    if (t >= T_) return;
    const float* xr = g_x1 + (size_t)t * D_;
    float acc[E_];
    #pragma unroll
    for (int e = 0; e < E_; e++) acc[e] = 0.f;
    for (int d = lane; d < D_; d += 32) {
        float xv = xr[d];
        const float* gw = gateW + (size_t)d * E_;
        #pragma unroll
        for (int e = 0; e < E_; e++) acc[e] += xv * gw[e];
    }
    #pragma unroll
    for (int e = 0; e < E_; e++) {
        #pragma unroll
        for (int o = 16; o > 0; o >>= 1)
            acc[e] += __shfl_down_sync(0xffffffffu, acc[e], o);
    }
    if (lane == 0) {
        float p[E_];
        float mx = -1e30f;
        #pragma unroll
        for (int e = 0; e < E_; e++) { acc[e] += gateb[e]; mx = fmaxf(mx, acc[e]); }
        float ssum = 0.f;
        #pragma unroll
        for (int e = 0; e < E_; e++) { p[e] = expf(acc[e] - mx); ssum += p[e]; }
        float invs = 1.f / ssum;
        #pragma unroll
        for (int e = 0; e < E_; e++) { p[e] *= invs; atomicAdd(&g_rsum[e], p[e]); }
        int i0 = 0;
        #pragma unroll
        for (int e = 1; e < E_; e++) if (p[e] > p[i0]) i0 = e;
        int i1 = -1;
        #pragma unroll
        for (int e = 0; e < E_; e++)
            if (e != i0 && (i1 < 0 || p[e] > p[i1])) i1 = e;
        float wsum = p[i0] + p[i1];
        int pos0 = atomicAdd(&g_cnt[i0], 1);
        int pos1 = atomicAdd(&g_cnt[i1], 1);
        g_texp[2*t]   = i0; g_tpos[2*t]   = pos0; g_tw[2*t]   = p[i0] / wsum;
        g_texp[2*t+1] = i1; g_tpos[2*t+1] = pos1; g_tw[2*t+1] = p[i1] / wsum;
    }
}

__global__ void k_scan() {
    if (threadIdx.x == 0 && blockIdx.x == 0) {
        int o = 0;
        for (int e = 0; e < E_; e++) {
            g_offs[e] = o;
            o += ((g_cnt[e] + 127) >> 7) << 7;
        }
        g_offs[E_] = o;
    }
}

__global__ void k_fill_slots() {
    int i = blockIdx.x * 256 + threadIdx.x;
    if (i >= T_ * TOPK_) return;
    int e = g_texp[i];
    int slot = g_offs[e] + g_tpos[i];
    g_slot_tok[slot]  = i >> 1;
    g_slot_rank[slot] = i & 1;
    g_slot_w[slot]    = g_tw[i];
}

__global__ void k_aux(float* __restrict__ out) {
    if (threadIdx.x == 0 && blockIdx.x == 0) {
        float a = 0.f;
        for (int e = 0; e < E_; e++)
            a += ((float)g_cnt[e] / (float)(T_ * TOPK_)) * (g_rsum[e] / (float)T_);
        out[0] = (float)E_ * a;
    }
}

// ------------------------- launch -------------------------
extern "C" void kernel_launch(void* const* d_in, const int* in_sizes, int n_in,
                              void* d_out, int out_size)
{
    const float* x     = (const float*)d_in[0];
    const float* Wq    = (const float*)d_in[1];
    const float* bq    = (const float*)d_in[2];
    const float* Wk    = (const float*)d_in[3];
    const float* bk    = (const float*)d_in[4];
    const float* Wv    = (const float*)d_in[5];
    const float* bv    = (const float*)d_in[6];
    const float* Wo    = (const float*)d_in[7];
    const float* bo    = (const float*)d_in[8];
    const float* g1    = (const float*)d_in[9];
    const float* beta1 = (const float*)d_in[10];
    const float* gateW = (const float*)d_in[11];
    const float* gateb = (const float*)d_in[12];
    const float* eW1   = (const float*)d_in[13];
    const float* eb1   = (const float*)d_in[14];
    const float* eW2   = (const float*)d_in[15];
    const float* eb2   = (const float*)d_in[16];
    const float* g2    = (const float*)d_in[17];
    const float* beta2 = (const float*)d_in[18];
    float* out = (float*)d_out;

    __half *pxhi,*pxlo,*pqhi,*pqlo,*pkhi,*pvthi,*pathi,*patlo,*px1hi,*phhi;
    __half *pWqh,*pWkh,*pWvh,*pWoh,*pW1h,*pW2h;
    float *pproj, *px1, *py;
    cudaGetSymbolAddress((void**)&pxhi,  g_xhi);  cudaGetSymbolAddress((void**)&pxlo,  g_xlo);
    cudaGetSymbolAddress((void**)&pqhi,  g_qhi);  cudaGetSymbolAddress((void**)&pqlo,  g_qlo);
    cudaGetSymbolAddress((void**)&pkhi,  g_khi);
    cudaGetSymbolAddress((void**)&pvthi, g_vthi);
    cudaGetSymbolAddress((void**)&pathi, g_athi); cudaGetSymbolAddress((void**)&patlo, g_atlo);
    cudaGetSymbolAddress((void**)&px1hi, g_x1hi);
    cudaGetSymbolAddress((void**)&phhi,  g_hhi);
    cudaGetSymbolAddress((void**)&pWqh,  g_Wqh);
    cudaGetSymbolAddress((void**)&pWkh,  g_Wkh);
    cudaGetSymbolAddress((void**)&pWvh,  g_Wvh);
    cudaGetSymbolAddress((void**)&pWoh,  g_Woh);
    cudaGetSymbolAddress((void**)&pW1h,  g_W1h);
    cudaGetSymbolAddress((void**)&pW2h,  g_W2h);
    cudaGetSymbolAddress((void**)&pproj, g_proj);
    cudaGetSymbolAddress((void**)&px1,   g_x1);
    cudaGetSymbolAddress((void**)&py,    g_y);

    const int SM_SPLIT  = (4*APL_ + 2*BPL_) * 2;   // 58368 B
    const int SM_SINGLE = (2*APL_ + 2*BPL_) * 2;   // 37888 B
    cudaFuncSetAttribute(k_gemm_hf<0,1>, cudaFuncAttributeMaxDynamicSharedMemorySize, SM_SPLIT);
    cudaFuncSetAttribute(k_gemm_hf<1,1>, cudaFuncAttributeMaxDynamicSharedMemorySize, SM_SPLIT);
    cudaFuncSetAttribute(k_gemm_hf<2,1>, cudaFuncAttributeMaxDynamicSharedMemorySize, SM_SPLIT);
    cudaFuncSetAttribute(k_gemm_hf<3,0>, cudaFuncAttributeMaxDynamicSharedMemorySize, SM_SINGLE);
    cudaFuncSetAttribute(k_gemm_hf<4,0>, cudaFuncAttributeMaxDynamicSharedMemorySize, SM_SINGLE);

    // --- pre-pass: split x; streaming-convert weights to fp16 (native [K,N] layout) ---
    k_asplit<<<(T_*D_/2 + 255)/256, 256>>>((const float2*)x, pxhi, pxlo, T_*D_/2);
    k_wcvt<<<(D_*D_/4 + 255)/256, 256>>>((const float4*)Wq, (uint2*)pWqh, D_*D_/4);
    k_wcvt<<<(D_*D_/4 + 255)/256, 256>>>((const float4*)Wk, (uint2*)pWkh, D_*D_/4);
    k_wcvt<<<(D_*D_/4 + 255)/256, 256>>>((const float4*)Wv, (uint2*)pWvh, D_*D_/4);
    k_wcvt<<<(D_*D_/4 + 255)/256, 256>>>((const float4*)Wo, (uint2*)pWoh, D_*D_/4);
    k_wcvt<<<(E_*D_*F_/4 + 255)/256, 256>>>((const float4*)eW1, (uint2*)pW1h, E_*D_*F_/4);
    k_wcvt<<<(E_*F_*D_/4 + 255)/256, 256>>>((const float4*)eW2, (uint2*)pW2h, E_*F_*D_/4);

    // --- attention block ---
    const float QSCALE = 0.125f * 1.4426950408889634f;   // 1/sqrt(HD) * log2(e)
    dim3 gproj(D_/128, T_/128);
    k_gemm_hf<1,1><<<gproj, 256, SM_SPLIT>>>(pxhi, pxlo, pWqh, bq, nullptr, pqhi, pqlo, T_, D_, D_, QSCALE);
    k_gemm_hf<1,1><<<gproj, 256, SM_SPLIT>>>(pxhi, pxlo, pWkh, bk, nullptr, pkhi, nullptr, T_, D_, D_, 1.f);
    k_gemm_hf<2,1><<<gproj, 256, SM_SPLIT>>>(pxhi, pxlo, pWvh, bv, nullptr, pvthi, nullptr, T_, D_, D_, 1.f);
    k_flash_hf<<<dim3(S_/64, H_, B_), 128>>>(pqhi, pqlo, pkhi, pvthi, pathi, patlo);
    k_gemm_hf<0,1><<<gproj, 256, SM_SPLIT>>>(pathi, patlo, pWoh, bo, pproj, nullptr, nullptr, T_, D_, D_, 1.f);
    k_add_ln<<<T_, 256>>>(x, pproj, g1, beta1, px1, px1hi);

    // --- MoE routing ---
    k_init_small<<<1, 32>>>();
    k_init_slots<<<(NSLOT_ + 255)/256, 256>>>();
    k_routing<<<T_/8, 256>>>(gateW, gateb);
    k_scan<<<1, 1>>>();
    k_fill_slots<<<(T_*TOPK_ + 255)/256, 256>>>();

    // --- expert FFN (single fp16, sparse top-2, 128-padded segments) ---
    k_gemm_hf<3,0><<<dim3(F_/128, NSLOT_/128), 256, SM_SINGLE>>>(px1hi, nullptr, pW1h, eb1, nullptr, phhi, nullptr, NSLOT_, F_, D_, 1.f);
    k_gemm_hf<4,0><<<dim3(D_/128, NSLOT_/128), 256, SM_SINGLE>>>(phhi, nullptr, pW2h, eb2, py, nullptr, nullptr, NSLOT_, D_, F_, 1.f);

    // --- final layernorm + aux loss ---
    k_ln3<<<T_, 256>>>(px1, py, g2, beta2, out);
    if (out_size > T_*D_) k_aux<<<1, 1>>>(out + (size_t)T_*D_);
}